// round 1
// baseline (speedup 1.0000x reference)
#include <cuda_runtime.h>
#include <cuda_bf16.h>
#include <math.h>

// ---------------------------------------------------------------------------
// Problem constants
// ---------------------------------------------------------------------------
#define BB        16
#define TT        8
#define NB        4
#define C_INC     2048       // C_IN
#define C_INR     512        // C_INNER
#define HH        14
#define WW        14
#define HWP       196        // H*W
#define FRAMES    128        // B*T
#define M_TOTAL   25088      // FRAMES*HW
#define K_FEATS   4608       // C_INNER*9
#define NROIS     512        // FRAMES*NB
#define NCLS      174
#define NOBJ      301

// Output layout in d_out (float32):
//   [0, 2784)            cls_out   (16 x 174)
//   [2784, 2784+9632)    obj_cls   (32 x 301)
//   [12416, 12448)       obj_labels (32, cast to float)
#define OUT_OBJCLS_OFF 2784
#define OUT_LABEL_OFF  12416

// ---------------------------------------------------------------------------
// Scratch (static __device__ arrays: allocation-free, per harness rules)
// ---------------------------------------------------------------------------
__device__ float g_fm[M_TOTAL * C_INR];        // [frame][hw][o]   51.4 MB
__device__ float g_feats[NROIS * K_FEATS];     // [roi][bin][c]     9.4 MB
__device__ float g_regacc[NROIS * C_INR];      // pre-bias GEMM2 accum
__device__ float g_pooled[BB * C_INR];
__device__ float g_objfeas[2 * BB * C_INR];
__device__ float g_hid_obj[2 * BB * C_INR];
__device__ float g_hid_cls[BB * C_INR];

// ---------------------------------------------------------------------------
// GEMM1: fm[m][n] = sum_k x_row(m)[k] * conv5_w[n][k]
//   m = frame*196 + hw ; x element at  b*(2048*1568) + k*1568 + t*196 + hw
//   128x128 block tile, 8x8 microtile, BK=8, 256 threads
// ---------------------------------------------------------------------------
__global__ __launch_bounds__(256, 2)
void gemm1_kernel(const float* __restrict__ x, const float* __restrict__ w)
{
    __shared__ float As[8][128];
    __shared__ float Bs[8][132];       // padded: avoids 8-way store conflicts
    __shared__ int   rowBase[128];

    const int tid = threadIdx.x;
    const int m0  = blockIdx.x * 128;
    const int n0  = blockIdx.y * 128;

    if (tid < 128) {
        int m     = m0 + tid;
        int frame = m / HWP;
        int hw    = m - frame * HWP;
        int b     = frame >> 3;
        int t     = frame & 7;
        rowBase[tid] = b * (C_INC * TT * HWP) + t * HWP + hw;
    }
    __syncthreads();

    float acc[8][8];
#pragma unroll
    for (int i = 0; i < 8; i++)
#pragma unroll
        for (int j = 0; j < 8; j++) acc[i][j] = 0.0f;

    const int ty = tid >> 4;     // 0..15
    const int tx = tid & 15;     // 0..15

    const int a_mm = tid & 127;
    const int a_kk = tid >> 7;   // 0..1
    const int aBase = rowBase[a_mm];

    const int b_kk = tid & 7;
    const int b_nn = tid >> 3;   // 0..31
    const long wBase = (long)(n0 + b_nn) * C_INC + b_kk;

    for (int k0 = 0; k0 < C_INC; k0 += 8) {
#pragma unroll
        for (int r = 0; r < 4; r++) {
            int kk = a_kk + r * 2;
            As[kk][a_mm] = x[aBase + (k0 + kk) * (TT * HWP)];
        }
#pragma unroll
        for (int r = 0; r < 4; r++) {
            Bs[b_kk][b_nn + r * 32] = w[wBase + (long)r * 32 * C_INC + k0];
        }
        __syncthreads();

#pragma unroll
        for (int kk = 0; kk < 8; kk++) {
            float av[8], bv[8];
            *(float4*)&av[0] = *(const float4*)&As[kk][ty * 8];
            *(float4*)&av[4] = *(const float4*)&As[kk][ty * 8 + 4];
            *(float4*)&bv[0] = *(const float4*)&Bs[kk][tx * 8];
            *(float4*)&bv[4] = *(const float4*)&Bs[kk][tx * 8 + 4];
#pragma unroll
            for (int i = 0; i < 8; i++)
#pragma unroll
                for (int j = 0; j < 8; j++)
                    acc[i][j] = fmaf(av[i], bv[j], acc[i][j]);
        }
        __syncthreads();
    }

#pragma unroll
    for (int i = 0; i < 8; i++) {
        int m = m0 + ty * 8 + i;
        float4 o0 = make_float4(acc[i][0], acc[i][1], acc[i][2], acc[i][3]);
        float4 o1 = make_float4(acc[i][4], acc[i][5], acc[i][6], acc[i][7]);
        *(float4*)&g_fm[(long)m * C_INR + n0 + tx * 8]     = o0;
        *(float4*)&g_fm[(long)m * C_INR + n0 + tx * 8 + 4] = o1;
    }
}

// ---------------------------------------------------------------------------
// ROI align: one block per ROI, 128 threads = 128 float4 channel groups.
// Writes feats[roi][bin*512 + c] (bin-major so writes are coalesced).
// ---------------------------------------------------------------------------
__global__ __launch_bounds__(128)
void roi_kernel(const float* __restrict__ boxes)
{
    const int r     = blockIdx.x;       // 0..511  ( = frame*4 + nb )
    const int frame = r >> 2;
    const int c4    = threadIdx.x;      // 0..127

    const float* bx = boxes + r * 4;
    float cx = bx[0], cy = bx[1], w = bx[2], h = bx[3];

    // corners in image coords, then * scale (14/224 = 0.0625) — mirror ref ops
    float x1 = ((cx - w * 0.5f) * 224.0f) * 0.0625f;
    float y1 = ((cy - h * 0.5f) * 224.0f) * 0.0625f;
    float x2 = ((cx + w * 0.5f) * 224.0f) * 0.0625f;
    float y2 = ((cy + h * 0.5f) * 224.0f) * 0.0625f;

    float roi_w = fmaxf(x2 - x1, 1.0f);
    float roi_h = fmaxf(y2 - y1, 1.0f);
    float bw = roi_w * (1.0f / 3.0f);
    float bh = roi_h * (1.0f / 3.0f);

    float4 acc[9];
#pragma unroll
    for (int i = 0; i < 9; i++) acc[i] = make_float4(0.f, 0.f, 0.f, 0.f);

    const float* fmf = g_fm + (long)frame * HWP * C_INR + c4 * 4;

#pragma unroll
    for (int iy = 0; iy < 6; iy++) {
        float yy = y1 + (float)(iy >> 1) * bh + ((float)(iy & 1) + 0.5f) * bh * 0.5f;
        bool vy = (yy > -1.0f) && (yy < 14.0f);
        float yc = fminf(fmaxf(yy, 0.0f), 13.0f);
        int   yi0 = (int)floorf(yc);
        int   yi1 = min(yi0 + 1, 13);
        float ly = yc - (float)yi0;
        float hy = 1.0f - ly;

#pragma unroll
        for (int ix = 0; ix < 6; ix++) {
            float xx = x1 + (float)(ix >> 1) * bw + ((float)(ix & 1) + 0.5f) * bw * 0.5f;
            bool v = vy && (xx > -1.0f) && (xx < 14.0f);
            if (!v) continue;
            float xc = fminf(fmaxf(xx, 0.0f), 13.0f);
            int   xi0 = (int)floorf(xc);
            int   xi1 = min(xi0 + 1, 13);
            float lx = xc - (float)xi0;
            float hx = 1.0f - lx;

            float w00 = hy * hx, w01 = hy * lx, w10 = ly * hx, w11 = ly * lx;

            float4 p00 = *(const float4*)(fmf + (yi0 * WW + xi0) * C_INR);
            float4 p01 = *(const float4*)(fmf + (yi0 * WW + xi1) * C_INR);
            float4 p10 = *(const float4*)(fmf + (yi1 * WW + xi0) * C_INR);
            float4 p11 = *(const float4*)(fmf + (yi1 * WW + xi1) * C_INR);

            int bin = (iy >> 1) * 3 + (ix >> 1);
            acc[bin].x += w00 * p00.x + w01 * p01.x + w10 * p10.x + w11 * p11.x;
            acc[bin].y += w00 * p00.y + w01 * p01.y + w10 * p10.y + w11 * p11.y;
            acc[bin].z += w00 * p00.z + w01 * p01.z + w10 * p10.z + w11 * p11.z;
            acc[bin].w += w00 * p00.w + w01 * p01.w + w10 * p10.w + w11 * p11.w;
        }
    }

    float* out = g_feats + (long)r * K_FEATS + c4 * 4;
#pragma unroll
    for (int bin = 0; bin < 9; bin++) {
        float4 o = acc[bin];
        o.x *= 0.25f; o.y *= 0.25f; o.z *= 0.25f; o.w *= 0.25f;
        *(float4*)(out + bin * C_INR) = o;
    }
}

// ---------------------------------------------------------------------------
// zero g_regacc
// ---------------------------------------------------------------------------
__global__ void zero_kernel()
{
    int i = blockIdx.x * blockDim.x + threadIdx.x;
    if (i < NROIS * C_INR) g_regacc[i] = 0.0f;
}

// ---------------------------------------------------------------------------
// GEMM2 (split-K=4, atomicAdd): regacc[r][j] += feats[r][k'] * re_w[perm(k')][j]
//   feats k' = bin*512 + c  maps to re_w row  c*9 + bin
//   64x64 tile, 4x4 microtile, BK=16, 256 threads, grid (8,8,4)
// ---------------------------------------------------------------------------
__global__ __launch_bounds__(256)
void gemm2_kernel(const float* __restrict__ re_w)
{
    __shared__ float As[16][68];   // padded
    __shared__ float Bs[16][64];

    const int tid = threadIdx.x;
    const int m0 = blockIdx.x * 64;
    const int n0 = blockIdx.y * 64;
    const int kbase = blockIdx.z * (K_FEATS / 4);   // 1152

    float acc[4][4];
#pragma unroll
    for (int i = 0; i < 4; i++)
#pragma unroll
        for (int j = 0; j < 4; j++) acc[i][j] = 0.0f;

    const int ty = tid >> 4, tx = tid & 15;
    const int a_kk = tid & 15, a_mm0 = tid >> 4;   // mm = a_mm0 + r*16
    const int b_nn = tid & 63, b_kk0 = tid >> 6;   // kk = b_kk0 + r*4

    for (int k0 = kbase; k0 < kbase + (K_FEATS / 4); k0 += 16) {
#pragma unroll
        for (int r = 0; r < 4; r++) {
            As[a_kk][a_mm0 + r * 16] =
                g_feats[(long)(m0 + a_mm0 + r * 16) * K_FEATS + k0 + a_kk];
        }
#pragma unroll
        for (int r = 0; r < 4; r++) {
            int kk = b_kk0 + r * 4;
            int kp = k0 + kk;
            int row = (kp & 511) * 9 + (kp >> 9);    // perm into re_w rows
            Bs[kk][b_nn] = re_w[(long)row * C_INR + n0 + b_nn];
        }
        __syncthreads();

#pragma unroll
        for (int kk = 0; kk < 16; kk++) {
            float4 a = *(const float4*)&As[kk][ty * 4];
            float4 b = *(const float4*)&Bs[kk][tx * 4];
            float av[4] = {a.x, a.y, a.z, a.w};
            float bv[4] = {b.x, b.y, b.z, b.w};
#pragma unroll
            for (int i = 0; i < 4; i++)
#pragma unroll
                for (int j = 0; j < 4; j++)
                    acc[i][j] = fmaf(av[i], bv[j], acc[i][j]);
        }
        __syncthreads();
    }

#pragma unroll
    for (int i = 0; i < 4; i++)
#pragma unroll
        for (int j = 0; j < 4; j++)
            atomicAdd(&g_regacc[(long)(m0 + ty * 4 + i) * C_INR + n0 + tx * 4 + j],
                      acc[i][j]);
}

// ---------------------------------------------------------------------------
// Reduce: reg = relu(acc + re_b); mean over T; pooled mean over NB;
// obj selection (stable argsort of 2) + labels.  grid 16 (b), 512 threads (j)
// ---------------------------------------------------------------------------
__global__ __launch_bounds__(512)
void reduce_kernel(const float* __restrict__ re_b, const int* __restrict__ cat,
                   float* __restrict__ out, int out_size)
{
    const int b = blockIdx.x;
    const int j = threadIdx.x;
    const float bias = re_b[j];

    float rm[NB];
    float p = 0.0f;
#pragma unroll
    for (int nb = 0; nb < NB; nb++) {
        float s = 0.0f;
#pragma unroll
        for (int t = 0; t < TT; t++) {
            int r = (b * TT + t) * NB + nb;
            s += fmaxf(g_regacc[(long)r * C_INR + j] + bias, 0.0f);
        }
        rm[nb] = s * 0.125f;
        p += rm[nb];
    }
    g_pooled[b * C_INR + j] = p * 0.25f;

    int c2 = cat[b * NB + 2];
    int c3 = cat[b * NB + 3];
    // stable argsort of [(c2==0),(c3==0)] ascending
    int o0 = (c2 == 0 && c3 != 0) ? 1 : 0;
    int o1 = 1 - o0;
    g_objfeas[(2 * b) * C_INR + j]     = rm[2 + o0];
    g_objfeas[(2 * b + 1) * C_INR + j] = rm[2 + o1];

    if (j == 0 && out_size >= OUT_LABEL_OFF + 2 * BB) {
        out[OUT_LABEL_OFF + 2 * b]     = (float)(o0 == 0 ? c2 : c3);
        out[OUT_LABEL_OFF + 2 * b + 1] = (float)(o1 == 0 ? c2 : c3);
    }
}

// ---------------------------------------------------------------------------
// Small dense layer: out[m][n] = bias[n] + sum_k X[m][k]*W[k][n]   (K == 512)
// grid (M, ceil(N/256)), 256 threads
// ---------------------------------------------------------------------------
__global__ __launch_bounds__(256)
void linear_kernel(const float* __restrict__ X, const float* __restrict__ W,
                   const float* __restrict__ bias, float* __restrict__ out, int N)
{
    __shared__ float xs[512];
    const int m = blockIdx.x;
    for (int k = threadIdx.x; k < 512; k += 256) xs[k] = X[m * 512 + k];
    __syncthreads();

    const int n = blockIdx.y * 256 + threadIdx.x;
    if (n < N) {
        float a = bias[n];
#pragma unroll 8
        for (int k = 0; k < 512; k++)
            a = fmaf(xs[k], __ldg(&W[(long)k * N + n]), a);
        out[m * N + n] = a;
    }
}

// ---------------------------------------------------------------------------
// kernel_launch
// ---------------------------------------------------------------------------
extern "C" void kernel_launch(void* const* d_in, const int* in_sizes, int n_in,
                              void* d_out, int out_size)
{
    const float* x       = (const float*)d_in[0];
    const float* boxes   = (const float*)d_in[1];
    const int*   cat     = (const int*)  d_in[2];
    const float* conv5_w = (const float*)d_in[3];
    const float* re_w    = (const float*)d_in[4];
    const float* re_b    = (const float*)d_in[5];
    const float* oc1_w   = (const float*)d_in[6];
    const float* oc1_b   = (const float*)d_in[7];
    const float* oc2_w   = (const float*)d_in[8];
    const float* oc2_b   = (const float*)d_in[9];
    const float* pr1_w   = (const float*)d_in[10];
    const float* pr1_b   = (const float*)d_in[11];
    const float* pr2_w   = (const float*)d_in[12];
    const float* pr2_b   = (const float*)d_in[13];
    float* out = (float*)d_out;

    // device addresses of scratch for pointer-taking kernels
    float *p_pooled, *p_objfeas, *p_hid_obj, *p_hid_cls;
    cudaGetSymbolAddress((void**)&p_pooled,  g_pooled);
    cudaGetSymbolAddress((void**)&p_objfeas, g_objfeas);
    cudaGetSymbolAddress((void**)&p_hid_obj, g_hid_obj);
    cudaGetSymbolAddress((void**)&p_hid_cls, g_hid_cls);

    // 1) big 1x1-conv GEMM: x @ conv5_w^T -> fm [frame][hw][o]
    gemm1_kernel<<<dim3(M_TOTAL / 128, C_INR / 128), 256>>>(x, conv5_w);

    // 2) ROI align -> feats [roi][bin][c]
    roi_kernel<<<NROIS, 128>>>(boxes);

    // 3) feats @ re_w (split-K with atomics)
    zero_kernel<<<(NROIS * C_INR + 255) / 256, 256>>>();
    gemm2_kernel<<<dim3(8, 8, 4), 256>>>(re_w);

    // 4) bias+relu+T-mean, NB-mean pool, obj selection + labels
    reduce_kernel<<<BB, 512>>>(re_b, cat, out, out_size);

    // 5) heads
    linear_kernel<<<dim3(2 * BB, 2), 256>>>(p_objfeas, oc1_w, oc1_b, p_hid_obj, 512);
    linear_kernel<<<dim3(2 * BB, 2), 256>>>(p_hid_obj, oc2_w, oc2_b, out + OUT_OBJCLS_OFF, NOBJ);
    linear_kernel<<<dim3(BB, 2), 256>>>(p_pooled, pr1_w, pr1_b, p_hid_cls, 512);
    linear_kernel<<<dim3(BB, 1), 256>>>(p_hid_cls, pr2_w, pr2_b, out, NCLS);
}

// round 4
// speedup vs baseline: 2.7365x; 2.7365x over previous
#include <cuda_runtime.h>
#include <cuda_bf16.h>
#include <math.h>
#include <stdint.h>

// ---------------------------------------------------------------------------
// Problem constants
// ---------------------------------------------------------------------------
#define BB        16
#define TT        8
#define NB        4
#define C_INC     2048       // C_IN
#define C_INR     512        // C_INNER
#define WW        14
#define HWP       196        // H*W
#define M_TOTAL   25088      // FRAMES*HW
#define K_FEATS   4608       // C_INNER*9
#define NROIS     512
#define NCLS      174
#define NOBJ      301

#define OUT_OBJCLS_OFF 2784
#define OUT_LABEL_OFF  12416

// ---------------------------------------------------------------------------
// Scratch
// ---------------------------------------------------------------------------
__device__ float g_fm[M_TOTAL * C_INR];        // [frame][hw][o]
__device__ float g_wtf[C_INR * C_INC];         // conv5_w rounded to tf32 (RN)
__device__ float g_feats[NROIS * K_FEATS];     // [roi][bin][c]
__device__ float g_regacc[NROIS * C_INR];
__device__ float g_pooled[BB * C_INR];
__device__ float g_objfeas[2 * BB * C_INR];
__device__ float g_hid_obj[2 * BB * C_INR];
__device__ float g_hid_cls[BB * C_INR];

// ---------------------------------------------------------------------------
// Helpers
// ---------------------------------------------------------------------------
__device__ __forceinline__ uint32_t smem_u32(const void* p) {
    uint32_t a;
    asm("{ .reg .u64 t; cvta.to.shared.u64 t, %1; cvt.u32.u64 %0, t; }"
        : "=r"(a) : "l"(p));
    return a;
}
__device__ __forceinline__ uint32_t f2tf32(float v) {
    uint32_t o;
    asm("cvt.rna.tf32.f32 %0, %1;" : "=r"(o) : "f"(v));
    return o;
}
#define LDS32(v, a) asm volatile("ld.shared.b32 %0, [%1];" : "=r"(v) : "r"(a))

__device__ __forceinline__ void mma_tf32(float& d0, float& d1, float& d2, float& d3,
                                         uint32_t a0, uint32_t a1, uint32_t a2, uint32_t a3,
                                         uint32_t b0, uint32_t b1)
{
    asm volatile(
        "mma.sync.aligned.m16n8k8.row.col.f32.tf32.tf32.f32 "
        "{%0,%1,%2,%3}, {%4,%5,%6,%7}, {%8,%9}, {%0,%1,%2,%3};"
        : "+f"(d0), "+f"(d1), "+f"(d2), "+f"(d3)
        : "r"(a0), "r"(a1), "r"(a2), "r"(a3), "r"(b0), "r"(b1));
}

// ---------------------------------------------------------------------------
// w -> tf32(RN) pre-pass
// ---------------------------------------------------------------------------
__global__ void wconv_kernel(const float* __restrict__ w)
{
    int i = blockIdx.x * blockDim.x + threadIdx.x;
    if (i < C_INR * C_INC)
        g_wtf[i] = __uint_as_float(f2tf32(w[i]));
}

// ---------------------------------------------------------------------------
// GEMM1 via mma.sync tf32: fm[m][n] = sum_k x(m,k) * w(n,k)
//   CTA tile 128x128, BK=32, 8 warps (2x4), warp tile 64x32.
//   SMEM: 128B rows, XOR-swizzled (chunk ^= (row&7)); A[m][k], B[n][k].
//   Buffers: A0 @0, A1 @16384, B0 @32768, B1 @49152  (64 KB total)
// ---------------------------------------------------------------------------
#define G1_ITERS   (C_INC / 32)     // 64
#define G1_SMEM    65536

__global__ void __launch_bounds__(256, 2) gemm1_mma(const float* __restrict__ x)
{
    extern __shared__ char sm[];
    const uint32_t sbase = smem_u32(sm);
    const int tid  = threadIdx.x;
    const int wid  = tid >> 5;
    const int lane = tid & 31;
    const int m0   = blockIdx.x * 128;
    const int n0   = blockIdx.y * 128;

    // ---- A loader mapping: thread covers m = tid&127, k in [kg, kg+16)
    const int lm = tid & 127;
    const int kgo = (tid >> 7) << 4;        // 0 or 16
    const float* xb;
    {
        int mm = m0 + lm;
        int frame = mm / HWP;
        int hw = mm - frame * HWP;
        int b = frame >> 3, t = frame & 7;
        xb = x + (size_t)b * (C_INC * TT * HWP) + (size_t)t * HWP + hw;
    }
    const uint32_t a_row = (uint32_t)lm * 128;
    const uint32_t a_sw  = ((uint32_t)lm & 7) << 4;

    // ---- warp tile constants
    const int wm = (wid >> 2) * 64;
    const int wn = (wid & 3) * 32;
    const int g  = lane >> 2;
    const int tg = lane & 3;
    const uint32_t frag_sw = ((uint32_t)g & 7) << 4;     // swizzle bits for frag rows
    const uint32_t aoff0 = (uint32_t)(wm + g) * 128;
    const uint32_t boff0 = (uint32_t)(wn + g) * 128 + 32768u;

    float acc[4][4][4];
#pragma unroll
    for (int i = 0; i < 4; i++)
#pragma unroll
        for (int j = 0; j < 4; j++)
#pragma unroll
            for (int r = 0; r < 4; r++) acc[i][j][r] = 0.0f;

    float ar[16];

    // ---------------- prologue: stage k0 = 0 into buf 0
#pragma unroll
    for (int j = 0; j < 16; ++j)
        ar[j] = xb[(size_t)(kgo + j) * (TT * HWP)];
#pragma unroll
    for (int j4 = 0; j4 < 4; ++j4) {
        uint32_t dst = sbase + a_row + ((((uint32_t)(kgo + j4 * 4)) * 4) ^ a_sw);
        uint4 v = make_uint4(f2tf32(ar[j4 * 4 + 0]), f2tf32(ar[j4 * 4 + 1]),
                             f2tf32(ar[j4 * 4 + 2]), f2tf32(ar[j4 * 4 + 3]));
        asm volatile("st.shared.v4.b32 [%0], {%1,%2,%3,%4};"
                     :: "r"(dst), "r"(v.x), "r"(v.y), "r"(v.z), "r"(v.w));
    }
#pragma unroll
    for (int i = 0; i < 4; ++i) {
        int idx = tid + i * 256;
        int n = idx >> 3, c = idx & 7;
        const float* src = g_wtf + (size_t)(n0 + n) * C_INC + c * 4;
        uint32_t dst = sbase + 32768u + (uint32_t)n * 128 + (((uint32_t)c * 16) ^ (((uint32_t)n & 7) << 4));
        asm volatile("cp.async.cg.shared.global [%0], [%1], 16;" :: "r"(dst), "l"(src));
    }
    asm volatile("cp.async.commit_group;" ::: "memory");

    // ---------------- main loop
    for (int s = 0; s < G1_ITERS; ++s) {
        const uint32_t bufo = (s & 1) ? 16384u : 0u;

        asm volatile("cp.async.wait_group 0;" ::: "memory");
        __syncthreads();

        if (s + 1 < G1_ITERS) {
            const int k0n = (s + 1) * 32;
            // A: issue LDGs early (latency hidden by compute below)
#pragma unroll
            for (int j = 0; j < 16; ++j)
                ar[j] = xb[(size_t)(k0n + kgo + j) * (TT * HWP)];
            // B: cp.async into the other buffer
            const uint32_t nb = (s + 1) & 1 ? 16384u : 0u;
#pragma unroll
            for (int i = 0; i < 4; ++i) {
                int idx = tid + i * 256;
                int n = idx >> 3, c = idx & 7;
                const float* src = g_wtf + (size_t)(n0 + n) * C_INC + k0n + c * 4;
                uint32_t dst = sbase + 32768u + nb + (uint32_t)n * 128
                             + (((uint32_t)c * 16) ^ (((uint32_t)n & 7) << 4));
                asm volatile("cp.async.cg.shared.global [%0], [%1], 16;" :: "r"(dst), "l"(src));
            }
            asm volatile("cp.async.commit_group;" ::: "memory");
        }

        // ---- compute on buffer s
        const uint32_t Ab = sbase + bufo;
        const uint32_t Bb = sbase + bufo;   // boff0 already carries +32768
#pragma unroll
        for (int kc = 0; kc < 4; ++kc) {
            const uint32_t u0 = (uint32_t)(kc * 32 + tg * 4) ^ frag_sw;
            const uint32_t u1 = (uint32_t)(kc * 32 + tg * 4 + 16) ^ frag_sw;

            uint32_t af[4][4];
#pragma unroll
            for (int mt = 0; mt < 4; ++mt) {
                uint32_t base = Ab + aoff0 + (uint32_t)mt * 2048;
                LDS32(af[mt][0], base + u0);
                LDS32(af[mt][1], base + 1024 + u0);
                LDS32(af[mt][2], base + u1);
                LDS32(af[mt][3], base + 1024 + u1);
            }
            uint32_t bf[4][2];
#pragma unroll
            for (int nt = 0; nt < 4; ++nt) {
                uint32_t base = Bb + boff0 + (uint32_t)nt * 1024;
                LDS32(bf[nt][0], base + u0);
                LDS32(bf[nt][1], base + u1);
            }
#pragma unroll
            for (int mt = 0; mt < 4; ++mt)
#pragma unroll
                for (int nt = 0; nt < 4; ++nt)
                    mma_tf32(acc[mt][nt][0], acc[mt][nt][1], acc[mt][nt][2], acc[mt][nt][3],
                             af[mt][0], af[mt][1], af[mt][2], af[mt][3],
                             bf[nt][0], bf[nt][1]);
        }

        // ---- store staged A into the other buffer
        if (s + 1 < G1_ITERS) {
            const uint32_t nb = (s + 1) & 1 ? 16384u : 0u;
#pragma unroll
            for (int j4 = 0; j4 < 4; ++j4) {
                uint32_t dst = sbase + nb + a_row + ((((uint32_t)(kgo + j4 * 4)) * 4) ^ a_sw);
                uint4 v = make_uint4(f2tf32(ar[j4 * 4 + 0]), f2tf32(ar[j4 * 4 + 1]),
                                     f2tf32(ar[j4 * 4 + 2]), f2tf32(ar[j4 * 4 + 3]));
                asm volatile("st.shared.v4.b32 [%0], {%1,%2,%3,%4};"
                             :: "r"(dst), "r"(v.x), "r"(v.y), "r"(v.z), "r"(v.w));
            }
        }
    }

    // ---------------- epilogue: acc -> g_fm
#pragma unroll
    for (int mt = 0; mt < 4; ++mt) {
#pragma unroll
        for (int nt = 0; nt < 4; ++nt) {
            int gm = m0 + wm + mt * 16 + g;
            int gn = n0 + wn + nt * 8 + tg * 2;
            float2 v0 = make_float2(acc[mt][nt][0], acc[mt][nt][1]);
            float2 v1 = make_float2(acc[mt][nt][2], acc[mt][nt][3]);
            *(float2*)&g_fm[(size_t)gm * C_INR + gn]       = v0;
            *(float2*)&g_fm[(size_t)(gm + 8) * C_INR + gn] = v1;
        }
    }
}

// ---------------------------------------------------------------------------
// ROI align: one block per ROI, 128 threads = 128 float4 channel groups
// ---------------------------------------------------------------------------
__global__ __launch_bounds__(128)
void roi_kernel(const float* __restrict__ boxes)
{
    const int r     = blockIdx.x;
    const int frame = r >> 2;
    const int c4    = threadIdx.x;

    const float* bx = boxes + r * 4;
    float cx = bx[0], cy = bx[1], w = bx[2], h = bx[3];

    float x1 = ((cx - w * 0.5f) * 224.0f) * 0.0625f;
    float y1 = ((cy - h * 0.5f) * 224.0f) * 0.0625f;
    float x2 = ((cx + w * 0.5f) * 224.0f) * 0.0625f;
    float y2 = ((cy + h * 0.5f) * 224.0f) * 0.0625f;

    float roi_w = fmaxf(x2 - x1, 1.0f);
    float roi_h = fmaxf(y2 - y1, 1.0f);
    float bw = roi_w * (1.0f / 3.0f);
    float bh = roi_h * (1.0f / 3.0f);

    float4 acc[9];
#pragma unroll
    for (int i = 0; i < 9; i++) acc[i] = make_float4(0.f, 0.f, 0.f, 0.f);

    const float* fmf = g_fm + (size_t)frame * HWP * C_INR + c4 * 4;

#pragma unroll
    for (int iy = 0; iy < 6; iy++) {
        float yy = y1 + (float)(iy >> 1) * bh + ((float)(iy & 1) + 0.5f) * bh * 0.5f;
        bool vy = (yy > -1.0f) && (yy < 14.0f);
        float yc = fminf(fmaxf(yy, 0.0f), 13.0f);
        int   yi0 = (int)floorf(yc);
        int   yi1 = min(yi0 + 1, 13);
        float ly = yc - (float)yi0;
        float hy = 1.0f - ly;

#pragma unroll
        for (int ix = 0; ix < 6; ix++) {
            float xx = x1 + (float)(ix >> 1) * bw + ((float)(ix & 1) + 0.5f) * bw * 0.5f;
            bool v = vy && (xx > -1.0f) && (xx < 14.0f);
            if (!v) continue;
            float xc = fminf(fmaxf(xx, 0.0f), 13.0f);
            int   xi0 = (int)floorf(xc);
            int   xi1 = min(xi0 + 1, 13);
            float lx = xc - (float)xi0;
            float hx = 1.0f - lx;

            float w00 = hy * hx, w01 = hy * lx, w10 = ly * hx, w11 = ly * lx;

            float4 p00 = *(const float4*)(fmf + (yi0 * WW + xi0) * C_INR);
            float4 p01 = *(const float4*)(fmf + (yi0 * WW + xi1) * C_INR);
            float4 p10 = *(const float4*)(fmf + (yi1 * WW + xi0) * C_INR);
            float4 p11 = *(const float4*)(fmf + (yi1 * WW + xi1) * C_INR);

            int bin = (iy >> 1) * 3 + (ix >> 1);
            acc[bin].x += w00 * p00.x + w01 * p01.x + w10 * p10.x + w11 * p11.x;
            acc[bin].y += w00 * p00.y + w01 * p01.y + w10 * p10.y + w11 * p11.y;
            acc[bin].z += w00 * p00.z + w01 * p01.z + w10 * p10.z + w11 * p11.z;
            acc[bin].w += w00 * p00.w + w01 * p01.w + w10 * p10.w + w11 * p11.w;
        }
    }

    float* out = g_feats + (size_t)r * K_FEATS + c4 * 4;
#pragma unroll
    for (int bin = 0; bin < 9; bin++) {
        float4 o = acc[bin];
        o.x *= 0.25f; o.y *= 0.25f; o.z *= 0.25f; o.w *= 0.25f;
        *(float4*)(out + bin * C_INR) = o;
    }
}

// ---------------------------------------------------------------------------
__global__ void zero_kernel()
{
    int i = blockIdx.x * blockDim.x + threadIdx.x;
    if (i < NROIS * C_INR) g_regacc[i] = 0.0f;
}

// ---------------------------------------------------------------------------
// GEMM2 (split-K=4, atomicAdd)
// ---------------------------------------------------------------------------
__global__ __launch_bounds__(256)
void gemm2_kernel(const float* __restrict__ re_w)
{
    __shared__ float As[16][68];
    __shared__ float Bs[16][64];

    const int tid = threadIdx.x;
    const int m0 = blockIdx.x * 64;
    const int n0 = blockIdx.y * 64;
    const int kbase = blockIdx.z * (K_FEATS / 4);

    float acc[4][4];
#pragma unroll
    for (int i = 0; i < 4; i++)
#pragma unroll
        for (int j = 0; j < 4; j++) acc[i][j] = 0.0f;

    const int ty = tid >> 4, tx = tid & 15;
    const int a_kk = tid & 15, a_mm0 = tid >> 4;
    const int b_nn = tid & 63, b_kk0 = tid >> 6;

    for (int k0 = kbase; k0 < kbase + (K_FEATS / 4); k0 += 16) {
#pragma unroll
        for (int r = 0; r < 4; r++) {
            As[a_kk][a_mm0 + r * 16] =
                g_feats[(size_t)(m0 + a_mm0 + r * 16) * K_FEATS + k0 + a_kk];
        }
#pragma unroll
        for (int r = 0; r < 4; r++) {
            int kkv = b_kk0 + r * 4;
            int kp = k0 + kkv;
            int row = (kp & 511) * 9 + (kp >> 9);
            Bs[kkv][b_nn] = re_w[(size_t)row * C_INR + n0 + b_nn];
        }
        __syncthreads();

#pragma unroll
        for (int kkv = 0; kkv < 16; kkv++) {
            float4 a = *(const float4*)&As[kkv][ty * 4];
            float4 b = *(const float4*)&Bs[kkv][tx * 4];
            float av[4] = {a.x, a.y, a.z, a.w};
            float bv[4] = {b.x, b.y, b.z, b.w};
#pragma unroll
            for (int i = 0; i < 4; i++)
#pragma unroll
                for (int j = 0; j < 4; j++)
                    acc[i][j] = fmaf(av[i], bv[j], acc[i][j]);
        }
        __syncthreads();
    }

#pragma unroll
    for (int i = 0; i < 4; i++)
#pragma unroll
        for (int j = 0; j < 4; j++)
            atomicAdd(&g_regacc[(size_t)(m0 + ty * 4 + i) * C_INR + n0 + tx * 4 + j],
                      acc[i][j]);
}

// ---------------------------------------------------------------------------
__global__ __launch_bounds__(512)
void reduce_kernel(const float* __restrict__ re_b, const int* __restrict__ cat,
                   float* __restrict__ out, int out_size)
{
    const int b = blockIdx.x;
    const int j = threadIdx.x;
    const float bias = re_b[j];

    float rm[NB];
    float p = 0.0f;
#pragma unroll
    for (int nb = 0; nb < NB; nb++) {
        float s = 0.0f;
#pragma unroll
        for (int t = 0; t < TT; t++) {
            int r = (b * TT + t) * NB + nb;
            s += fmaxf(g_regacc[(size_t)r * C_INR + j] + bias, 0.0f);
        }
        rm[nb] = s * 0.125f;
        p += rm[nb];
    }
    g_pooled[b * C_INR + j] = p * 0.25f;

    int c2 = cat[b * NB + 2];
    int c3 = cat[b * NB + 3];
    int o0 = (c2 == 0 && c3 != 0) ? 1 : 0;
    int o1 = 1 - o0;
    g_objfeas[(2 * b) * C_INR + j]     = rm[2 + o0];
    g_objfeas[(2 * b + 1) * C_INR + j] = rm[2 + o1];

    if (j == 0 && out_size >= OUT_LABEL_OFF + 2 * BB) {
        out[OUT_LABEL_OFF + 2 * b]     = (float)(o0 == 0 ? c2 : c3);
        out[OUT_LABEL_OFF + 2 * b + 1] = (float)(o1 == 0 ? c2 : c3);
    }
}

// ---------------------------------------------------------------------------
__global__ __launch_bounds__(256)
void linear_kernel(const float* __restrict__ X, const float* __restrict__ W,
                   const float* __restrict__ bias, float* __restrict__ out, int N)
{
    __shared__ float xs[512];
    const int m = blockIdx.x;
    for (int k = threadIdx.x; k < 512; k += 256) xs[k] = X[m * 512 + k];
    __syncthreads();

    const int n = blockIdx.y * 256 + threadIdx.x;
    if (n < N) {
        float a = bias[n];
#pragma unroll 8
        for (int k = 0; k < 512; k++)
            a = fmaf(xs[k], __ldg(&W[(size_t)k * N + n]), a);
        out[m * N + n] = a;
    }
}

// ---------------------------------------------------------------------------
// kernel_launch
// ---------------------------------------------------------------------------
extern "C" void kernel_launch(void* const* d_in, const int* in_sizes, int n_in,
                              void* d_out, int out_size)
{
    const float* x       = (const float*)d_in[0];
    const float* boxes   = (const float*)d_in[1];
    const int*   cat     = (const int*)  d_in[2];
    const float* conv5_w = (const float*)d_in[3];
    const float* re_w    = (const float*)d_in[4];
    const float* re_b    = (const float*)d_in[5];
    const float* oc1_w   = (const float*)d_in[6];
    const float* oc1_b   = (const float*)d_in[7];
    const float* oc2_w   = (const float*)d_in[8];
    const float* oc2_b   = (const float*)d_in[9];
    const float* pr1_w   = (const float*)d_in[10];
    const float* pr1_b   = (const float*)d_in[11];
    const float* pr2_w   = (const float*)d_in[12];
    const float* pr2_b   = (const float*)d_in[13];
    float* out = (float*)d_out;

    float *p_pooled, *p_objfeas, *p_hid_obj, *p_hid_cls;
    cudaGetSymbolAddress((void**)&p_pooled,  g_pooled);
    cudaGetSymbolAddress((void**)&p_objfeas, g_objfeas);
    cudaGetSymbolAddress((void**)&p_hid_obj, g_hid_obj);
    cudaGetSymbolAddress((void**)&p_hid_cls, g_hid_cls);

    cudaFuncSetAttribute(gemm1_mma, cudaFuncAttributeMaxDynamicSharedMemorySize, G1_SMEM);

    // 0) round w to tf32 (RN) once per launch
    wconv_kernel<<<(C_INR * C_INC + 511) / 512, 512>>>(conv5_w);

    // 1) big 1x1-conv GEMM on tensor cores (mma.sync tf32)
    gemm1_mma<<<dim3(M_TOTAL / 128, C_INR / 128), 256, G1_SMEM>>>(x);

    // 2) ROI align
    roi_kernel<<<NROIS, 128>>>(boxes);

    // 3) feats @ re_w (split-K with atomics)
    zero_kernel<<<(NROIS * C_INR + 255) / 256, 256>>>();
    gemm2_kernel<<<dim3(8, 8, 4), 256>>>(re_w);

    // 4) bias+relu+T-mean, NB-mean pool, obj selection + labels
    reduce_kernel<<<BB, 512>>>(re_b, cat, out, out_size);

    // 5) heads
    linear_kernel<<<dim3(2 * BB, 2), 256>>>(p_objfeas, oc1_w, oc1_b, p_hid_obj, 512);
    linear_kernel<<<dim3(2 * BB, 2), 256>>>(p_hid_obj, oc2_w, oc2_b, out + OUT_OBJCLS_OFF, NOBJ);
    linear_kernel<<<dim3(BB, 2), 256>>>(p_pooled, pr1_w, pr1_b, p_hid_cls, 512);
    linear_kernel<<<dim3(BB, 1), 256>>>(p_hid_cls, pr2_w, pr2_b, out, NCLS);
}

// round 5
// speedup vs baseline: 3.0651x; 1.1201x over previous
#include <cuda_runtime.h>
#include <cuda_bf16.h>
#include <math.h>
#include <stdint.h>

// ---------------------------------------------------------------------------
// Problem constants
// ---------------------------------------------------------------------------
#define BB        16
#define TT        8
#define NB        4
#define C_INC     2048       // C_IN
#define C_INR     512        // C_INNER
#define WW        14
#define HWP       196        // H*W
#define M_TOTAL   25088      // FRAMES*HW
#define K_FEATS   4608       // C_INNER*9
#define NROIS     512
#define NCLS      174
#define NOBJ      301

#define OUT_OBJCLS_OFF 2784
#define OUT_LABEL_OFF  12416

// ---------------------------------------------------------------------------
// Scratch
// ---------------------------------------------------------------------------
__device__ float g_fm[M_TOTAL * C_INR];        // [frame][hw][o]
__device__ float g_wtf[C_INR * C_INC];         // conv5_w tf32(RN), [n][k]
__device__ float g_rewtf[C_INR * K_FEATS];     // re_w permuted+transposed tf32, [n][k]
__device__ float g_feats[NROIS * K_FEATS];     // [roi][bin][c], tf32-rounded
__device__ float g_regacc[NROIS * C_INR];
__device__ float g_pooled[BB * C_INR];
__device__ float g_objfeas[2 * BB * C_INR];
__device__ float g_hid_obj[2 * BB * C_INR];
__device__ float g_hid_cls[BB * C_INR];

// ---------------------------------------------------------------------------
// Helpers
// ---------------------------------------------------------------------------
__device__ __forceinline__ uint32_t smem_u32(const void* p) {
    uint32_t a;
    asm("{ .reg .u64 t; cvta.to.shared.u64 t, %1; cvt.u32.u64 %0, t; }"
        : "=r"(a) : "l"(p));
    return a;
}
__device__ __forceinline__ uint32_t f2tf32(float v) {
    uint32_t o;
    asm("cvt.rna.tf32.f32 %0, %1;" : "=r"(o) : "f"(v));
    return o;
}
#define LDS32(v, a) asm volatile("ld.shared.b32 %0, [%1];" : "=r"(v) : "r"(a))

__device__ __forceinline__ void mma_tf32(float& d0, float& d1, float& d2, float& d3,
                                         uint32_t a0, uint32_t a1, uint32_t a2, uint32_t a3,
                                         uint32_t b0, uint32_t b1)
{
    asm volatile(
        "mma.sync.aligned.m16n8k8.row.col.f32.tf32.tf32.f32 "
        "{%0,%1,%2,%3}, {%4,%5,%6,%7}, {%8,%9}, {%0,%1,%2,%3};"
        : "+f"(d0), "+f"(d1), "+f"(d2), "+f"(d3)
        : "r"(a0), "r"(a1), "r"(a2), "r"(a3), "r"(b0), "r"(b1));
}

// ---------------------------------------------------------------------------
// Weight pre-passes: round to tf32(RN); re_w also permuted+transposed
// ---------------------------------------------------------------------------
__global__ void wconv_kernel(const float* __restrict__ w)
{
    int i = blockIdx.x * blockDim.x + threadIdx.x;
    if (i < C_INR * C_INC)
        g_wtf[i] = __uint_as_float(f2tf32(w[i]));
}

// g_rewtf[n][k] = tf32( re_w[(k%512)*9 + k/512][n] )
__global__ void rewconv_kernel(const float* __restrict__ rw)
{
    int i = blockIdx.x * blockDim.x + threadIdx.x;
    if (i < C_INR * K_FEATS) {
        int n = i / K_FEATS;
        int k = i - n * K_FEATS;
        int row = (k & 511) * 9 + (k >> 9);
        g_rewtf[i] = __uint_as_float(f2tf32(rw[(size_t)row * C_INR + n]));
    }
}

// ---------------------------------------------------------------------------
// GEMM1 via mma.sync tf32: fm[m][n] = sum_k x(m,k) * w(n,k)
//   CTA tile 128x128, BK=32, 8 warps (2x4), warp tile 64x32.
//   grid (4 n-blocks, 196 m-blocks): same-m CTAs adjacent -> A-tile L2 sharing
// ---------------------------------------------------------------------------
#define G1_ITERS   (C_INC / 32)     // 64
#define G1_SMEM    65536

__global__ void __launch_bounds__(256, 2) gemm1_mma(const float* __restrict__ x)
{
    extern __shared__ char sm[];
    const uint32_t sbase = smem_u32(sm);
    const int tid  = threadIdx.x;
    const int wid  = tid >> 5;
    const int lane = tid & 31;
    const int n0   = blockIdx.x * 128;   // swapped: n fastest
    const int m0   = blockIdx.y * 128;

    // ---- A loader mapping: thread covers m = tid&127, k in [kg, kg+16)
    const int lm = tid & 127;
    const int kgo = (tid >> 7) << 4;        // 0 or 16
    const float* xb;
    {
        int mm = m0 + lm;
        int frame = mm / HWP;
        int hw = mm - frame * HWP;
        int b = frame >> 3, t = frame & 7;
        xb = x + (size_t)b * (C_INC * TT * HWP) + (size_t)t * HWP + hw;
    }
    const uint32_t a_row = (uint32_t)lm * 128;
    const uint32_t a_sw  = ((uint32_t)lm & 7) << 4;

    // ---- warp tile constants
    const int wm = (wid >> 2) * 64;
    const int wn = (wid & 3) * 32;
    const int g  = lane >> 2;
    const int tg = lane & 3;
    const uint32_t frag_sw = ((uint32_t)g & 7) << 4;
    const uint32_t aoff0 = (uint32_t)(wm + g) * 128;
    const uint32_t boff0 = (uint32_t)(wn + g) * 128 + 32768u;

    float acc[4][4][4];
#pragma unroll
    for (int i = 0; i < 4; i++)
#pragma unroll
        for (int j = 0; j < 4; j++)
#pragma unroll
            for (int r = 0; r < 4; r++) acc[i][j][r] = 0.0f;

    float ar[16];

    // ---------------- prologue: stage k0 = 0 into buf 0
#pragma unroll
    for (int j = 0; j < 16; ++j)
        ar[j] = xb[(size_t)(kgo + j) * (TT * HWP)];
#pragma unroll
    for (int j4 = 0; j4 < 4; ++j4) {
        uint32_t dst = sbase + a_row + ((((uint32_t)(kgo + j4 * 4)) * 4) ^ a_sw);
        uint4 v = make_uint4(f2tf32(ar[j4 * 4 + 0]), f2tf32(ar[j4 * 4 + 1]),
                             f2tf32(ar[j4 * 4 + 2]), f2tf32(ar[j4 * 4 + 3]));
        asm volatile("st.shared.v4.b32 [%0], {%1,%2,%3,%4};"
                     :: "r"(dst), "r"(v.x), "r"(v.y), "r"(v.z), "r"(v.w));
    }
#pragma unroll
    for (int i = 0; i < 4; ++i) {
        int idx = tid + i * 256;
        int n = idx >> 3, c = idx & 7;
        const float* src = g_wtf + (size_t)(n0 + n) * C_INC + c * 4;
        uint32_t dst = sbase + 32768u + (uint32_t)n * 128 + (((uint32_t)c * 16) ^ (((uint32_t)n & 7) << 4));
        asm volatile("cp.async.cg.shared.global [%0], [%1], 16;" :: "r"(dst), "l"(src));
    }
    asm volatile("cp.async.commit_group;" ::: "memory");

    // ---------------- main loop
    for (int s = 0; s < G1_ITERS; ++s) {
        const uint32_t bufo = (s & 1) ? 16384u : 0u;

        asm volatile("cp.async.wait_group 0;" ::: "memory");
        __syncthreads();

        if (s + 1 < G1_ITERS) {
            const int k0n = (s + 1) * 32;
#pragma unroll
            for (int j = 0; j < 16; ++j)
                ar[j] = xb[(size_t)(k0n + kgo + j) * (TT * HWP)];
            const uint32_t nb = (s + 1) & 1 ? 16384u : 0u;
#pragma unroll
            for (int i = 0; i < 4; ++i) {
                int idx = tid + i * 256;
                int n = idx >> 3, c = idx & 7;
                const float* src = g_wtf + (size_t)(n0 + n) * C_INC + k0n + c * 4;
                uint32_t dst = sbase + 32768u + nb + (uint32_t)n * 128
                             + (((uint32_t)c * 16) ^ (((uint32_t)n & 7) << 4));
                asm volatile("cp.async.cg.shared.global [%0], [%1], 16;" :: "r"(dst), "l"(src));
            }
            asm volatile("cp.async.commit_group;" ::: "memory");
        }

        // ---- compute on buffer s
        const uint32_t Ab = sbase + bufo;
        const uint32_t Bb = sbase + bufo;
#pragma unroll
        for (int kc = 0; kc < 4; ++kc) {
            const uint32_t u0 = (uint32_t)(kc * 32 + tg * 4) ^ frag_sw;
            const uint32_t u1 = (uint32_t)(kc * 32 + tg * 4 + 16) ^ frag_sw;

            uint32_t af[4][4];
#pragma unroll
            for (int mt = 0; mt < 4; ++mt) {
                uint32_t base = Ab + aoff0 + (uint32_t)mt * 2048;
                LDS32(af[mt][0], base + u0);
                LDS32(af[mt][1], base + 1024 + u0);
                LDS32(af[mt][2], base + u1);
                LDS32(af[mt][3], base + 1024 + u1);
            }
            uint32_t bf[4][2];
#pragma unroll
            for (int nt = 0; nt < 4; ++nt) {
                uint32_t base = Bb + boff0 + (uint32_t)nt * 1024;
                LDS32(bf[nt][0], base + u0);
                LDS32(bf[nt][1], base + u1);
            }
#pragma unroll
            for (int mt = 0; mt < 4; ++mt)
#pragma unroll
                for (int nt = 0; nt < 4; ++nt)
                    mma_tf32(acc[mt][nt][0], acc[mt][nt][1], acc[mt][nt][2], acc[mt][nt][3],
                             af[mt][0], af[mt][1], af[mt][2], af[mt][3],
                             bf[nt][0], bf[nt][1]);
        }

        if (s + 1 < G1_ITERS) {
            const uint32_t nb = (s + 1) & 1 ? 16384u : 0u;
#pragma unroll
            for (int j4 = 0; j4 < 4; ++j4) {
                uint32_t dst = sbase + nb + a_row + ((((uint32_t)(kgo + j4 * 4)) * 4) ^ a_sw);
                uint4 v = make_uint4(f2tf32(ar[j4 * 4 + 0]), f2tf32(ar[j4 * 4 + 1]),
                                     f2tf32(ar[j4 * 4 + 2]), f2tf32(ar[j4 * 4 + 3]));
                asm volatile("st.shared.v4.b32 [%0], {%1,%2,%3,%4};"
                             :: "r"(dst), "r"(v.x), "r"(v.y), "r"(v.z), "r"(v.w));
            }
        }
    }

    // ---------------- epilogue
#pragma unroll
    for (int mt = 0; mt < 4; ++mt) {
#pragma unroll
        for (int nt = 0; nt < 4; ++nt) {
            int gm = m0 + wm + mt * 16 + g;
            int gn = n0 + wn + nt * 8 + tg * 2;
            float2 v0 = make_float2(acc[mt][nt][0], acc[mt][nt][1]);
            float2 v1 = make_float2(acc[mt][nt][2], acc[mt][nt][3]);
            *(float2*)&g_fm[(size_t)gm * C_INR + gn]       = v0;
            *(float2*)&g_fm[(size_t)(gm + 8) * C_INR + gn] = v1;
        }
    }
}

// ---------------------------------------------------------------------------
// ROI align: one block per ROI; outputs rounded to tf32 for gemm2
// ---------------------------------------------------------------------------
__global__ __launch_bounds__(128)
void roi_kernel(const float* __restrict__ boxes)
{
    const int r     = blockIdx.x;
    const int frame = r >> 2;
    const int c4    = threadIdx.x;

    const float* bx = boxes + r * 4;
    float cx = bx[0], cy = bx[1], w = bx[2], h = bx[3];

    float x1 = ((cx - w * 0.5f) * 224.0f) * 0.0625f;
    float y1 = ((cy - h * 0.5f) * 224.0f) * 0.0625f;
    float x2 = ((cx + w * 0.5f) * 224.0f) * 0.0625f;
    float y2 = ((cy + h * 0.5f) * 224.0f) * 0.0625f;

    float roi_w = fmaxf(x2 - x1, 1.0f);
    float roi_h = fmaxf(y2 - y1, 1.0f);
    float bw = roi_w * (1.0f / 3.0f);
    float bh = roi_h * (1.0f / 3.0f);

    float4 acc[9];
#pragma unroll
    for (int i = 0; i < 9; i++) acc[i] = make_float4(0.f, 0.f, 0.f, 0.f);

    const float* fmf = g_fm + (size_t)frame * HWP * C_INR + c4 * 4;

#pragma unroll
    for (int iy = 0; iy < 6; iy++) {
        float yy = y1 + (float)(iy >> 1) * bh + ((float)(iy & 1) + 0.5f) * bh * 0.5f;
        bool vy = (yy > -1.0f) && (yy < 14.0f);
        float yc = fminf(fmaxf(yy, 0.0f), 13.0f);
        int   yi0 = (int)floorf(yc);
        int   yi1 = min(yi0 + 1, 13);
        float ly = yc - (float)yi0;
        float hy = 1.0f - ly;

#pragma unroll
        for (int ix = 0; ix < 6; ix++) {
            float xx = x1 + (float)(ix >> 1) * bw + ((float)(ix & 1) + 0.5f) * bw * 0.5f;
            bool v = vy && (xx > -1.0f) && (xx < 14.0f);
            if (!v) continue;
            float xc = fminf(fmaxf(xx, 0.0f), 13.0f);
            int   xi0 = (int)floorf(xc);
            int   xi1 = min(xi0 + 1, 13);
            float lx = xc - (float)xi0;
            float hx = 1.0f - lx;

            float w00 = hy * hx, w01 = hy * lx, w10 = ly * hx, w11 = ly * lx;

            float4 p00 = *(const float4*)(fmf + (yi0 * WW + xi0) * C_INR);
            float4 p01 = *(const float4*)(fmf + (yi0 * WW + xi1) * C_INR);
            float4 p10 = *(const float4*)(fmf + (yi1 * WW + xi0) * C_INR);
            float4 p11 = *(const float4*)(fmf + (yi1 * WW + xi1) * C_INR);

            int bin = (iy >> 1) * 3 + (ix >> 1);
            acc[bin].x += w00 * p00.x + w01 * p01.x + w10 * p10.x + w11 * p11.x;
            acc[bin].y += w00 * p00.y + w01 * p01.y + w10 * p10.y + w11 * p11.y;
            acc[bin].z += w00 * p00.z + w01 * p01.z + w10 * p10.z + w11 * p11.z;
            acc[bin].w += w00 * p00.w + w01 * p01.w + w10 * p10.w + w11 * p11.w;
        }
    }

    float* out = g_feats + (size_t)r * K_FEATS + c4 * 4;
#pragma unroll
    for (int bin = 0; bin < 9; bin++) {
        float4 o = acc[bin];
        o.x = __uint_as_float(f2tf32(o.x * 0.25f));
        o.y = __uint_as_float(f2tf32(o.y * 0.25f));
        o.z = __uint_as_float(f2tf32(o.z * 0.25f));
        o.w = __uint_as_float(f2tf32(o.w * 0.25f));
        *(float4*)(out + bin * C_INR) = o;
    }
}

// ---------------------------------------------------------------------------
__global__ void zero_kernel()
{
    int i = blockIdx.x * blockDim.x + threadIdx.x;
    if (i < NROIS * C_INR) g_regacc[i] = 0.0f;
}

// ---------------------------------------------------------------------------
// GEMM2 via mma.sync tf32, split-K=8: regacc[m][n] += feats[m][k]*rewtf[n][k]
//   Same 128x128x32 pipeline as gemm1, but both tiles via cp.async.
//   grid (4 m, 4 n, 8 z); 18 iters each; fp32 atomicAdd epilogue.
// ---------------------------------------------------------------------------
#define G2_SPLITS 8
#define G2_KC     (K_FEATS / G2_SPLITS)   // 576
#define G2_ITERS  (G2_KC / 32)            // 18
#define G2_SMEM   65536

__global__ void __launch_bounds__(256, 2) gemm2_mma()
{
    extern __shared__ char sm[];
    const uint32_t sbase = smem_u32(sm);
    const int tid  = threadIdx.x;
    const int wid  = tid >> 5;
    const int lane = tid & 31;
    const int m0   = blockIdx.x * 128;
    const int n0   = blockIdx.y * 128;
    const int kb   = blockIdx.z * G2_KC;

    const int wm = (wid >> 2) * 64;
    const int wn = (wid & 3) * 32;
    const int g  = lane >> 2;
    const int tg = lane & 3;
    const uint32_t frag_sw = ((uint32_t)g & 7) << 4;
    const uint32_t aoff0 = (uint32_t)(wm + g) * 128;
    const uint32_t boff0 = (uint32_t)(wn + g) * 128 + 32768u;

    float acc[4][4][4];
#pragma unroll
    for (int i = 0; i < 4; i++)
#pragma unroll
        for (int j = 0; j < 4; j++)
#pragma unroll
            for (int r = 0; r < 4; r++) acc[i][j][r] = 0.0f;

    // loader mapping: idx -> (row, 16B-chunk); 4 chunks per thread per tile
    const int lrow = tid >> 1;              // shared by A and B loaders? No:
    // use idx scheme identical to gemm1 B loader for both tiles.

    // ---------------- prologue: stage k = kb into buf 0
#pragma unroll
    for (int i = 0; i < 4; ++i) {
        int idx = tid + i * 256;
        int rr = idx >> 3, c = idx & 7;
        uint32_t sw = (((uint32_t)c * 16) ^ (((uint32_t)rr & 7) << 4));
        const float* asrc = g_feats + (size_t)(m0 + rr) * K_FEATS + kb + c * 4;
        const float* bsrc = g_rewtf + (size_t)(n0 + rr) * K_FEATS + kb + c * 4;
        uint32_t adst = sbase + (uint32_t)rr * 128 + sw;
        uint32_t bdst = sbase + 32768u + (uint32_t)rr * 128 + sw;
        asm volatile("cp.async.cg.shared.global [%0], [%1], 16;" :: "r"(adst), "l"(asrc));
        asm volatile("cp.async.cg.shared.global [%0], [%1], 16;" :: "r"(bdst), "l"(bsrc));
    }
    asm volatile("cp.async.commit_group;" ::: "memory");

    for (int s = 0; s < G2_ITERS; ++s) {
        const uint32_t bufo = (s & 1) ? 16384u : 0u;

        asm volatile("cp.async.wait_group 0;" ::: "memory");
        __syncthreads();

        if (s + 1 < G2_ITERS) {
            const int k0n = kb + (s + 1) * 32;
            const uint32_t nb = (s + 1) & 1 ? 16384u : 0u;
#pragma unroll
            for (int i = 0; i < 4; ++i) {
                int idx = tid + i * 256;
                int rr = idx >> 3, c = idx & 7;
                uint32_t sw = (((uint32_t)c * 16) ^ (((uint32_t)rr & 7) << 4));
                const float* asrc = g_feats + (size_t)(m0 + rr) * K_FEATS + k0n + c * 4;
                const float* bsrc = g_rewtf + (size_t)(n0 + rr) * K_FEATS + k0n + c * 4;
                uint32_t adst = sbase + nb + (uint32_t)rr * 128 + sw;
                uint32_t bdst = sbase + 32768u + nb + (uint32_t)rr * 128 + sw;
                asm volatile("cp.async.cg.shared.global [%0], [%1], 16;" :: "r"(adst), "l"(asrc));
                asm volatile("cp.async.cg.shared.global [%0], [%1], 16;" :: "r"(bdst), "l"(bsrc));
            }
            asm volatile("cp.async.commit_group;" ::: "memory");
        }

        const uint32_t Ab = sbase + bufo;
        const uint32_t Bb = sbase + bufo;
#pragma unroll
        for (int kc = 0; kc < 4; ++kc) {
            const uint32_t u0 = (uint32_t)(kc * 32 + tg * 4) ^ frag_sw;
            const uint32_t u1 = (uint32_t)(kc * 32 + tg * 4 + 16) ^ frag_sw;

            uint32_t af[4][4];
#pragma unroll
            for (int mt = 0; mt < 4; ++mt) {
                uint32_t base = Ab + aoff0 + (uint32_t)mt * 2048;
                LDS32(af[mt][0], base + u0);
                LDS32(af[mt][1], base + 1024 + u0);
                LDS32(af[mt][2], base + u1);
                LDS32(af[mt][3], base + 1024 + u1);
            }
            uint32_t bf[4][2];
#pragma unroll
            for (int nt = 0; nt < 4; ++nt) {
                uint32_t base = Bb + boff0 + (uint32_t)nt * 1024;
                LDS32(bf[nt][0], base + u0);
                LDS32(bf[nt][1], base + u1);
            }
#pragma unroll
            for (int mt = 0; mt < 4; ++mt)
#pragma unroll
                for (int nt = 0; nt < 4; ++nt)
                    mma_tf32(acc[mt][nt][0], acc[mt][nt][1], acc[mt][nt][2], acc[mt][nt][3],
                             af[mt][0], af[mt][1], af[mt][2], af[mt][3],
                             bf[nt][0], bf[nt][1]);
        }
    }

    // ---------------- epilogue: atomic accumulate (split-K)
#pragma unroll
    for (int mt = 0; mt < 4; ++mt) {
#pragma unroll
        for (int nt = 0; nt < 4; ++nt) {
            int gm = m0 + wm + mt * 16 + g;
            int gn = n0 + wn + nt * 8 + tg * 2;
            atomicAdd(&g_regacc[(size_t)gm * C_INR + gn],           acc[mt][nt][0]);
            atomicAdd(&g_regacc[(size_t)gm * C_INR + gn + 1],       acc[mt][nt][1]);
            atomicAdd(&g_regacc[(size_t)(gm + 8) * C_INR + gn],     acc[mt][nt][2]);
            atomicAdd(&g_regacc[(size_t)(gm + 8) * C_INR + gn + 1], acc[mt][nt][3]);
        }
    }
}

// ---------------------------------------------------------------------------
__global__ __launch_bounds__(512)
void reduce_kernel(const float* __restrict__ re_b, const int* __restrict__ cat,
                   float* __restrict__ out, int out_size)
{
    const int b = blockIdx.x;
    const int j = threadIdx.x;
    const float bias = re_b[j];

    float rm[NB];
    float p = 0.0f;
#pragma unroll
    for (int nb = 0; nb < NB; nb++) {
        float s = 0.0f;
#pragma unroll
        for (int t = 0; t < TT; t++) {
            int r = (b * TT + t) * NB + nb;
            s += fmaxf(g_regacc[(size_t)r * C_INR + j] + bias, 0.0f);
        }
        rm[nb] = s * 0.125f;
        p += rm[nb];
    }
    g_pooled[b * C_INR + j] = p * 0.25f;

    int c2 = cat[b * NB + 2];
    int c3 = cat[b * NB + 3];
    int o0 = (c2 == 0 && c3 != 0) ? 1 : 0;
    int o1 = 1 - o0;
    g_objfeas[(2 * b) * C_INR + j]     = rm[2 + o0];
    g_objfeas[(2 * b + 1) * C_INR + j] = rm[2 + o1];

    if (j == 0 && out_size >= OUT_LABEL_OFF + 2 * BB) {
        out[OUT_LABEL_OFF + 2 * b]     = (float)(o0 == 0 ? c2 : c3);
        out[OUT_LABEL_OFF + 2 * b + 1] = (float)(o1 == 0 ? c2 : c3);
    }
}

// ---------------------------------------------------------------------------
__global__ __launch_bounds__(256)
void linear_kernel(const float* __restrict__ X, const float* __restrict__ W,
                   const float* __restrict__ bias, float* __restrict__ out, int N)
{
    __shared__ float xs[512];
    const int m = blockIdx.x;
    for (int k = threadIdx.x; k < 512; k += 256) xs[k] = X[m * 512 + k];
    __syncthreads();

    const int n = blockIdx.y * 256 + threadIdx.x;
    if (n < N) {
        float a = bias[n];
#pragma unroll 8
        for (int k = 0; k < 512; k++)
            a = fmaf(xs[k], __ldg(&W[(size_t)k * N + n]), a);
        out[m * N + n] = a;
    }
}

// ---------------------------------------------------------------------------
// kernel_launch
// ---------------------------------------------------------------------------
extern "C" void kernel_launch(void* const* d_in, const int* in_sizes, int n_in,
                              void* d_out, int out_size)
{
    const float* x       = (const float*)d_in[0];
    const float* boxes   = (const float*)d_in[1];
    const int*   cat     = (const int*)  d_in[2];
    const float* conv5_w = (const float*)d_in[3];
    const float* re_w    = (const float*)d_in[4];
    const float* re_b    = (const float*)d_in[5];
    const float* oc1_w   = (const float*)d_in[6];
    const float* oc1_b   = (const float*)d_in[7];
    const float* oc2_w   = (const float*)d_in[8];
    const float* oc2_b   = (const float*)d_in[9];
    const float* pr1_w   = (const float*)d_in[10];
    const float* pr1_b   = (const float*)d_in[11];
    const float* pr2_w   = (const float*)d_in[12];
    const float* pr2_b   = (const float*)d_in[13];
    float* out = (float*)d_out;

    float *p_pooled, *p_objfeas, *p_hid_obj, *p_hid_cls;
    cudaGetSymbolAddress((void**)&p_pooled,  g_pooled);
    cudaGetSymbolAddress((void**)&p_objfeas, g_objfeas);
    cudaGetSymbolAddress((void**)&p_hid_obj, g_hid_obj);
    cudaGetSymbolAddress((void**)&p_hid_cls, g_hid_cls);

    cudaFuncSetAttribute(gemm1_mma, cudaFuncAttributeMaxDynamicSharedMemorySize, G1_SMEM);
    cudaFuncSetAttribute(gemm2_mma, cudaFuncAttributeMaxDynamicSharedMemorySize, G2_SMEM);

    // 0) weight pre-passes (also zero regacc early, off the critical path)
    wconv_kernel<<<(C_INR * C_INC + 511) / 512, 512>>>(conv5_w);
    rewconv_kernel<<<(C_INR * K_FEATS + 511) / 512, 512>>>(re_w);
    zero_kernel<<<(NROIS * C_INR + 255) / 256, 256>>>();

    // 1) big 1x1-conv GEMM (tf32 mma); n-blocks adjacent for L2 A-sharing
    gemm1_mma<<<dim3(C_INR / 128, M_TOTAL / 128), 256, G1_SMEM>>>(x);

    // 2) ROI align (emits tf32-rounded feats)
    roi_kernel<<<NROIS, 128>>>(boxes);

    // 3) feats @ re_w on tensor cores, split-K=8 + atomics
    gemm2_mma<<<dim3(4, 4, G2_SPLITS), 256, G2_SMEM>>>();

    // 4) bias+relu+T-mean, NB-mean pool, obj selection + labels
    reduce_kernel<<<BB, 512>>>(re_b, cat, out, out_size);

    // 5) heads
    linear_kernel<<<dim3(2 * BB, 2), 256>>>(p_objfeas, oc1_w, oc1_b, p_hid_obj, 512);
    linear_kernel<<<dim3(2 * BB, 2), 256>>>(p_hid_obj, oc2_w, oc2_b, out + OUT_OBJCLS_OFF, NOBJ);
    linear_kernel<<<dim3(BB, 2), 256>>>(p_pooled, pr1_w, pr1_b, p_hid_cls, 512);
    linear_kernel<<<dim3(BB, 1), 256>>>(p_hid_cls, pr2_w, pr2_b, out, NCLS);
}

// round 6
// speedup vs baseline: 3.2422x; 1.0578x over previous
#include <cuda_runtime.h>
#include <cuda_bf16.h>
#include <math.h>
#include <stdint.h>

// ---------------------------------------------------------------------------
// Problem constants
// ---------------------------------------------------------------------------
#define BB        16
#define TT        8
#define NB        4
#define C_INC     2048       // C_IN
#define C_INR     512        // C_INNER
#define WW        14
#define HWP       196        // H*W
#define M_TOTAL   25088      // FRAMES*HW
#define K_FEATS   4608       // C_INNER*9
#define NROIS     512
#define NCLS      174
#define NOBJ      301

#define OUT_OBJCLS_OFF 2784
#define OUT_LABEL_OFF  12416

// ---------------------------------------------------------------------------
// Scratch
// ---------------------------------------------------------------------------
__device__ float g_fm[M_TOTAL * C_INR];        // [frame][hw][o]
__device__ float g_wtf[C_INR * C_INC];         // conv5_w tf32(RN), [n][k]
__device__ float g_rewt[C_INR * K_FEATS];      // re_w^T tf32, [n][k'], k'=c*9+bin
__device__ float g_feats[NROIS * K_FEATS];     // [roi][k'=c*9+bin], tf32-rounded
__device__ float g_regacc[NROIS * C_INR];
__device__ float g_pooled[BB * C_INR];
__device__ float g_objfeas[2 * BB * C_INR];
__device__ float g_hid_obj[2 * BB * C_INR];
__device__ float g_hid_cls[BB * C_INR];

// ---------------------------------------------------------------------------
// Helpers
// ---------------------------------------------------------------------------
__device__ __forceinline__ uint32_t smem_u32(const void* p) {
    uint32_t a;
    asm("{ .reg .u64 t; cvta.to.shared.u64 t, %1; cvt.u32.u64 %0, t; }"
        : "=r"(a) : "l"(p));
    return a;
}
__device__ __forceinline__ uint32_t f2tf32(float v) {
    uint32_t o;
    asm("cvt.rna.tf32.f32 %0, %1;" : "=r"(o) : "f"(v));
    return o;
}
#define LDS32(v, a) asm volatile("ld.shared.b32 %0, [%1];" : "=r"(v) : "r"(a))

__device__ __forceinline__ void mma_tf32(float& d0, float& d1, float& d2, float& d3,
                                         uint32_t a0, uint32_t a1, uint32_t a2, uint32_t a3,
                                         uint32_t b0, uint32_t b1)
{
    asm volatile(
        "mma.sync.aligned.m16n8k8.row.col.f32.tf32.tf32.f32 "
        "{%0,%1,%2,%3}, {%4,%5,%6,%7}, {%8,%9}, {%0,%1,%2,%3};"
        : "+f"(d0), "+f"(d1), "+f"(d2), "+f"(d3)
        : "r"(a0), "r"(a1), "r"(a2), "r"(a3), "r"(b0), "r"(b1));
}

// ---------------------------------------------------------------------------
// Weight pre-passes
// ---------------------------------------------------------------------------
__global__ void wconv_kernel(const float* __restrict__ w)
{
    int i = blockIdx.x * blockDim.x + threadIdx.x;
    if (i < C_INR * C_INC)
        g_wtf[i] = __uint_as_float(f2tf32(w[i]));
}

// Plain tiled transpose: g_rewt[n][r] = tf32( re_w[r][n] ),  r = k' = c*9+bin
__global__ void rewt_kernel(const float* __restrict__ rw)
{
    __shared__ float t[32][33];
    const int r0 = blockIdx.x * 32;     // row dim (4608)
    const int c0 = blockIdx.y * 32;     // n dim (512)
    const int cx = threadIdx.x;         // 0..31
    const int ty = threadIdx.y;         // 0..7
#pragma unroll
    for (int j = 0; j < 4; ++j) {
        int ry = ty + j * 8;
        t[ry][cx] = rw[(size_t)(r0 + ry) * C_INR + c0 + cx];
    }
    __syncthreads();
#pragma unroll
    for (int j = 0; j < 4; ++j) {
        int ry = ty + j * 8;
        g_rewt[(size_t)(c0 + ry) * K_FEATS + r0 + cx] =
            __uint_as_float(f2tf32(t[cx][ry]));
    }
}

// ---------------------------------------------------------------------------
// GEMM1 via mma.sync tf32: fm[m][n] = sum_k x(m,k) * w(n,k)
//   CTA tile 128x128, BK=32, 4 warps (2x2), warp tile 64x64.
//   grid (4 n-blocks, 196 m-blocks). SMEM 64KB double-buffered.
// ---------------------------------------------------------------------------
#define G1_ITERS   (C_INC / 32)     // 64
#define G1_SMEM    65536

__global__ void __launch_bounds__(128, 2) gemm1_mma(const float* __restrict__ x)
{
    extern __shared__ char sm[];
    const uint32_t sbase = smem_u32(sm);
    const int tid  = threadIdx.x;       // 0..127
    const int wid  = tid >> 5;
    const int lane = tid & 31;
    const int n0   = blockIdx.x * 128;
    const int m0   = blockIdx.y * 128;

    // ---- A loader: one m per thread, all 32 k's per iter
    const int lm = tid;
    const float* xb;
    {
        int mm = m0 + lm;
        int frame = mm / HWP;
        int hw = mm - frame * HWP;
        int b = frame >> 3, t = frame & 7;
        xb = x + (size_t)b * (C_INC * TT * HWP) + (size_t)t * HWP + hw;
    }
    const uint32_t a_row = (uint32_t)lm * 128;
    const uint32_t a_sw  = ((uint32_t)lm & 7) << 4;

    // ---- warp tile constants: 2x2 warps, warp 64x64
    const int wm = (wid >> 1) * 64;
    const int wn = (wid & 1) * 64;
    const int g  = lane >> 2;
    const int tg = lane & 3;
    const uint32_t frag_sw = ((uint32_t)g & 7) << 4;
    const uint32_t aoff0 = (uint32_t)(wm + g) * 128;
    const uint32_t boff0 = (uint32_t)(wn + g) * 128 + 32768u;

    float acc[4][8][4];
#pragma unroll
    for (int i = 0; i < 4; i++)
#pragma unroll
        for (int j = 0; j < 8; j++)
#pragma unroll
            for (int r = 0; r < 4; r++) acc[i][j][r] = 0.0f;

    float ar[32];

    // ---------------- prologue: stage k0 = 0 into buf 0
#pragma unroll
    for (int j = 0; j < 32; ++j)
        ar[j] = xb[(size_t)j * (TT * HWP)];
#pragma unroll
    for (int j4 = 0; j4 < 8; ++j4) {
        uint32_t dst = sbase + a_row + ((((uint32_t)j4 * 16)) ^ a_sw);
        uint4 v = make_uint4(f2tf32(ar[j4 * 4 + 0]), f2tf32(ar[j4 * 4 + 1]),
                             f2tf32(ar[j4 * 4 + 2]), f2tf32(ar[j4 * 4 + 3]));
        asm volatile("st.shared.v4.b32 [%0], {%1,%2,%3,%4};"
                     :: "r"(dst), "r"(v.x), "r"(v.y), "r"(v.z), "r"(v.w));
    }
#pragma unroll
    for (int i = 0; i < 8; ++i) {
        int idx = tid + i * 128;
        int n = idx >> 3, c = idx & 7;
        const float* src = g_wtf + (size_t)(n0 + n) * C_INC + c * 4;
        uint32_t dst = sbase + 32768u + (uint32_t)n * 128
                     + (((uint32_t)c * 16) ^ (((uint32_t)n & 7) << 4));
        asm volatile("cp.async.cg.shared.global [%0], [%1], 16;" :: "r"(dst), "l"(src));
    }
    asm volatile("cp.async.commit_group;" ::: "memory");

    // ---------------- main loop
    for (int s = 0; s < G1_ITERS; ++s) {
        const uint32_t bufo = (s & 1) ? 16384u : 0u;

        asm volatile("cp.async.wait_group 0;" ::: "memory");
        __syncthreads();

        if (s + 1 < G1_ITERS) {
            const int k0n = (s + 1) * 32;
#pragma unroll
            for (int j = 0; j < 32; ++j)
                ar[j] = xb[(size_t)(k0n + j) * (TT * HWP)];
            const uint32_t nb = (s + 1) & 1 ? 16384u : 0u;
#pragma unroll
            for (int i = 0; i < 8; ++i) {
                int idx = tid + i * 128;
                int n = idx >> 3, c = idx & 7;
                const float* src = g_wtf + (size_t)(n0 + n) * C_INC + k0n + c * 4;
                uint32_t dst = sbase + 32768u + nb + (uint32_t)n * 128
                             + (((uint32_t)c * 16) ^ (((uint32_t)n & 7) << 4));
                asm volatile("cp.async.cg.shared.global [%0], [%1], 16;" :: "r"(dst), "l"(src));
            }
            asm volatile("cp.async.commit_group;" ::: "memory");
        }

        // ---- compute on buffer s
        const uint32_t Ab = sbase + bufo;
        const uint32_t Bb = sbase + bufo;
#pragma unroll
        for (int kc = 0; kc < 4; ++kc) {
            const uint32_t u0 = (uint32_t)(kc * 32 + tg * 4) ^ frag_sw;
            const uint32_t u1 = (uint32_t)(kc * 32 + tg * 4 + 16) ^ frag_sw;

            uint32_t af[4][4];
#pragma unroll
            for (int mt = 0; mt < 4; ++mt) {
                uint32_t base = Ab + aoff0 + (uint32_t)mt * 2048;
                LDS32(af[mt][0], base + u0);
                LDS32(af[mt][1], base + 1024 + u0);
                LDS32(af[mt][2], base + u1);
                LDS32(af[mt][3], base + 1024 + u1);
            }
            uint32_t bf[8][2];
#pragma unroll
            for (int nt = 0; nt < 8; ++nt) {
                uint32_t base = Bb + boff0 + (uint32_t)nt * 1024;
                LDS32(bf[nt][0], base + u0);
                LDS32(bf[nt][1], base + u1);
            }
#pragma unroll
            for (int mt = 0; mt < 4; ++mt)
#pragma unroll
                for (int nt = 0; nt < 8; ++nt)
                    mma_tf32(acc[mt][nt][0], acc[mt][nt][1], acc[mt][nt][2], acc[mt][nt][3],
                             af[mt][0], af[mt][1], af[mt][2], af[mt][3],
                             bf[nt][0], bf[nt][1]);
        }

        // ---- store staged A into the other buffer
        if (s + 1 < G1_ITERS) {
            const uint32_t nb = (s + 1) & 1 ? 16384u : 0u;
#pragma unroll
            for (int j4 = 0; j4 < 8; ++j4) {
                uint32_t dst = sbase + nb + a_row + ((((uint32_t)j4 * 16)) ^ a_sw);
                uint4 v = make_uint4(f2tf32(ar[j4 * 4 + 0]), f2tf32(ar[j4 * 4 + 1]),
                                     f2tf32(ar[j4 * 4 + 2]), f2tf32(ar[j4 * 4 + 3]));
                asm volatile("st.shared.v4.b32 [%0], {%1,%2,%3,%4};"
                             :: "r"(dst), "r"(v.x), "r"(v.y), "r"(v.z), "r"(v.w));
            }
        }
    }

    // ---------------- epilogue
#pragma unroll
    for (int mt = 0; mt < 4; ++mt) {
#pragma unroll
        for (int nt = 0; nt < 8; ++nt) {
            int gm = m0 + wm + mt * 16 + g;
            int gn = n0 + wn + nt * 8 + tg * 2;
            float2 v0 = make_float2(acc[mt][nt][0], acc[mt][nt][1]);
            float2 v1 = make_float2(acc[mt][nt][2], acc[mt][nt][3]);
            *(float2*)&g_fm[(size_t)gm * C_INR + gn]       = v0;
            *(float2*)&g_fm[(size_t)(gm + 8) * C_INR + gn] = v1;
        }
    }
}

// ---------------------------------------------------------------------------
// ROI align: one block per ROI; writes feats in k' = c*9+bin order (tf32)
// ---------------------------------------------------------------------------
__global__ __launch_bounds__(128)
void roi_kernel(const float* __restrict__ boxes)
{
    const int r     = blockIdx.x;
    const int frame = r >> 2;
    const int c4    = threadIdx.x;

    const float* bx = boxes + r * 4;
    float cx = bx[0], cy = bx[1], w = bx[2], h = bx[3];

    float x1 = ((cx - w * 0.5f) * 224.0f) * 0.0625f;
    float y1 = ((cy - h * 0.5f) * 224.0f) * 0.0625f;
    float x2 = ((cx + w * 0.5f) * 224.0f) * 0.0625f;
    float y2 = ((cy + h * 0.5f) * 224.0f) * 0.0625f;

    float roi_w = fmaxf(x2 - x1, 1.0f);
    float roi_h = fmaxf(y2 - y1, 1.0f);
    float bw = roi_w * (1.0f / 3.0f);
    float bh = roi_h * (1.0f / 3.0f);

    float4 acc[9];
#pragma unroll
    for (int i = 0; i < 9; i++) acc[i] = make_float4(0.f, 0.f, 0.f, 0.f);

    const float* fmf = g_fm + (size_t)frame * HWP * C_INR + c4 * 4;

#pragma unroll
    for (int iy = 0; iy < 6; iy++) {
        float yy = y1 + (float)(iy >> 1) * bh + ((float)(iy & 1) + 0.5f) * bh * 0.5f;
        bool vy = (yy > -1.0f) && (yy < 14.0f);
        float yc = fminf(fmaxf(yy, 0.0f), 13.0f);
        int   yi0 = (int)floorf(yc);
        int   yi1 = min(yi0 + 1, 13);
        float ly = yc - (float)yi0;
        float hy = 1.0f - ly;

#pragma unroll
        for (int ix = 0; ix < 6; ix++) {
            float xx = x1 + (float)(ix >> 1) * bw + ((float)(ix & 1) + 0.5f) * bw * 0.5f;
            bool v = vy && (xx > -1.0f) && (xx < 14.0f);
            if (!v) continue;
            float xc = fminf(fmaxf(xx, 0.0f), 13.0f);
            int   xi0 = (int)floorf(xc);
            int   xi1 = min(xi0 + 1, 13);
            float lx = xc - (float)xi0;
            float hx = 1.0f - lx;

            float w00 = hy * hx, w01 = hy * lx, w10 = ly * hx, w11 = ly * lx;

            float4 p00 = *(const float4*)(fmf + (yi0 * WW + xi0) * C_INR);
            float4 p01 = *(const float4*)(fmf + (yi0 * WW + xi1) * C_INR);
            float4 p10 = *(const float4*)(fmf + (yi1 * WW + xi0) * C_INR);
            float4 p11 = *(const float4*)(fmf + (yi1 * WW + xi1) * C_INR);

            int bin = (iy >> 1) * 3 + (ix >> 1);
            acc[bin].x += w00 * p00.x + w01 * p01.x + w10 * p10.x + w11 * p11.x;
            acc[bin].y += w00 * p00.y + w01 * p01.y + w10 * p10.y + w11 * p11.y;
            acc[bin].z += w00 * p00.z + w01 * p01.z + w10 * p10.z + w11 * p11.z;
            acc[bin].w += w00 * p00.w + w01 * p01.w + w10 * p10.w + w11 * p11.w;
        }
    }

    // feats[k'] with k' = (c4*4+cc)*9 + bin -> thread-local 36 consecutive floats
    float tmp[36];
#pragma unroll
    for (int bin = 0; bin < 9; bin++) {
        tmp[0 * 9 + bin]  = __uint_as_float(f2tf32(acc[bin].x * 0.25f));
        tmp[1 * 9 + bin]  = __uint_as_float(f2tf32(acc[bin].y * 0.25f));
        tmp[2 * 9 + bin]  = __uint_as_float(f2tf32(acc[bin].z * 0.25f));
        tmp[3 * 9 + bin]  = __uint_as_float(f2tf32(acc[bin].w * 0.25f));
    }
    float* out = g_feats + (size_t)r * K_FEATS + c4 * 36;
#pragma unroll
    for (int q = 0; q < 9; q++)
        *(float4*)(out + q * 4) = *(float4*)&tmp[q * 4];
}

// ---------------------------------------------------------------------------
__global__ void zero_kernel()
{
    int i = blockIdx.x * blockDim.x + threadIdx.x;
    if (i < NROIS * C_INR) g_regacc[i] = 0.0f;
}

// ---------------------------------------------------------------------------
// GEMM2 via mma.sync tf32, split-K=8: regacc[m][n] += feats[m][k']*rewt[n][k']
// ---------------------------------------------------------------------------
#define G2_SPLITS 8
#define G2_KC     (K_FEATS / G2_SPLITS)   // 576
#define G2_ITERS  (G2_KC / 32)            // 18
#define G2_SMEM   65536

__global__ void __launch_bounds__(256, 2) gemm2_mma()
{
    extern __shared__ char sm[];
    const uint32_t sbase = smem_u32(sm);
    const int tid  = threadIdx.x;
    const int wid  = tid >> 5;
    const int lane = tid & 31;
    const int m0   = blockIdx.x * 128;
    const int n0   = blockIdx.y * 128;
    const int kb   = blockIdx.z * G2_KC;

    const int wm = (wid >> 2) * 64;
    const int wn = (wid & 3) * 32;
    const int g  = lane >> 2;
    const int tg = lane & 3;
    const uint32_t frag_sw = ((uint32_t)g & 7) << 4;
    const uint32_t aoff0 = (uint32_t)(wm + g) * 128;
    const uint32_t boff0 = (uint32_t)(wn + g) * 128 + 32768u;

    float acc[4][4][4];
#pragma unroll
    for (int i = 0; i < 4; i++)
#pragma unroll
        for (int j = 0; j < 4; j++)
#pragma unroll
            for (int r = 0; r < 4; r++) acc[i][j][r] = 0.0f;

    // ---------------- prologue: stage k = kb into buf 0
#pragma unroll
    for (int i = 0; i < 4; ++i) {
        int idx = tid + i * 256;
        int rr = idx >> 3, c = idx & 7;
        uint32_t sw = (((uint32_t)c * 16) ^ (((uint32_t)rr & 7) << 4));
        const float* asrc = g_feats + (size_t)(m0 + rr) * K_FEATS + kb + c * 4;
        const float* bsrc = g_rewt  + (size_t)(n0 + rr) * K_FEATS + kb + c * 4;
        uint32_t adst = sbase + (uint32_t)rr * 128 + sw;
        uint32_t bdst = sbase + 32768u + (uint32_t)rr * 128 + sw;
        asm volatile("cp.async.cg.shared.global [%0], [%1], 16;" :: "r"(adst), "l"(asrc));
        asm volatile("cp.async.cg.shared.global [%0], [%1], 16;" :: "r"(bdst), "l"(bsrc));
    }
    asm volatile("cp.async.commit_group;" ::: "memory");

    for (int s = 0; s < G2_ITERS; ++s) {
        const uint32_t bufo = (s & 1) ? 16384u : 0u;

        asm volatile("cp.async.wait_group 0;" ::: "memory");
        __syncthreads();

        if (s + 1 < G2_ITERS) {
            const int k0n = kb + (s + 1) * 32;
            const uint32_t nb = (s + 1) & 1 ? 16384u : 0u;
#pragma unroll
            for (int i = 0; i < 4; ++i) {
                int idx = tid + i * 256;
                int rr = idx >> 3, c = idx & 7;
                uint32_t sw = (((uint32_t)c * 16) ^ (((uint32_t)rr & 7) << 4));
                const float* asrc = g_feats + (size_t)(m0 + rr) * K_FEATS + k0n + c * 4;
                const float* bsrc = g_rewt  + (size_t)(n0 + rr) * K_FEATS + k0n + c * 4;
                uint32_t adst = sbase + nb + (uint32_t)rr * 128 + sw;
                uint32_t bdst = sbase + 32768u + nb + (uint32_t)rr * 128 + sw;
                asm volatile("cp.async.cg.shared.global [%0], [%1], 16;" :: "r"(adst), "l"(asrc));
                asm volatile("cp.async.cg.shared.global [%0], [%1], 16;" :: "r"(bdst), "l"(bsrc));
            }
            asm volatile("cp.async.commit_group;" ::: "memory");
        }

        const uint32_t Ab = sbase + bufo;
        const uint32_t Bb = sbase + bufo;
#pragma unroll
        for (int kc = 0; kc < 4; ++kc) {
            const uint32_t u0 = (uint32_t)(kc * 32 + tg * 4) ^ frag_sw;
            const uint32_t u1 = (uint32_t)(kc * 32 + tg * 4 + 16) ^ frag_sw;

            uint32_t af[4][4];
#pragma unroll
            for (int mt = 0; mt < 4; ++mt) {
                uint32_t base = Ab + aoff0 + (uint32_t)mt * 2048;
                LDS32(af[mt][0], base + u0);
                LDS32(af[mt][1], base + 1024 + u0);
                LDS32(af[mt][2], base + u1);
                LDS32(af[mt][3], base + 1024 + u1);
            }
            uint32_t bf[4][2];
#pragma unroll
            for (int nt = 0; nt < 4; ++nt) {
                uint32_t base = Bb + boff0 + (uint32_t)nt * 1024;
                LDS32(bf[nt][0], base + u0);
                LDS32(bf[nt][1], base + u1);
            }
#pragma unroll
            for (int mt = 0; mt < 4; ++mt)
#pragma unroll
                for (int nt = 0; nt < 4; ++nt)
                    mma_tf32(acc[mt][nt][0], acc[mt][nt][1], acc[mt][nt][2], acc[mt][nt][3],
                             af[mt][0], af[mt][1], af[mt][2], af[mt][3],
                             bf[nt][0], bf[nt][1]);
        }
    }

    // ---------------- epilogue: atomic accumulate (split-K)
#pragma unroll
    for (int mt = 0; mt < 4; ++mt) {
#pragma unroll
        for (int nt = 0; nt < 4; ++nt) {
            int gm = m0 + wm + mt * 16 + g;
            int gn = n0 + wn + nt * 8 + tg * 2;
            atomicAdd(&g_regacc[(size_t)gm * C_INR + gn],           acc[mt][nt][0]);
            atomicAdd(&g_regacc[(size_t)gm * C_INR + gn + 1],       acc[mt][nt][1]);
            atomicAdd(&g_regacc[(size_t)(gm + 8) * C_INR + gn],     acc[mt][nt][2]);
            atomicAdd(&g_regacc[(size_t)(gm + 8) * C_INR + gn + 1], acc[mt][nt][3]);
        }
    }
}

// ---------------------------------------------------------------------------
__global__ __launch_bounds__(512)
void reduce_kernel(const float* __restrict__ re_b, const int* __restrict__ cat,
                   float* __restrict__ out, int out_size)
{
    const int b = blockIdx.x;
    const int j = threadIdx.x;
    const float bias = re_b[j];

    float rm[NB];
    float p = 0.0f;
#pragma unroll
    for (int nb = 0; nb < NB; nb++) {
        float s = 0.0f;
#pragma unroll
        for (int t = 0; t < TT; t++) {
            int r = (b * TT + t) * NB + nb;
            s += fmaxf(g_regacc[(size_t)r * C_INR + j] + bias, 0.0f);
        }
        rm[nb] = s * 0.125f;
        p += rm[nb];
    }
    g_pooled[b * C_INR + j] = p * 0.25f;

    int c2 = cat[b * NB + 2];
    int c3 = cat[b * NB + 3];
    int o0 = (c2 == 0 && c3 != 0) ? 1 : 0;
    int o1 = 1 - o0;
    g_objfeas[(2 * b) * C_INR + j]     = rm[2 + o0];
    g_objfeas[(2 * b + 1) * C_INR + j] = rm[2 + o1];

    if (j == 0 && out_size >= OUT_LABEL_OFF + 2 * BB) {
        out[OUT_LABEL_OFF + 2 * b]     = (float)(o0 == 0 ? c2 : c3);
        out[OUT_LABEL_OFF + 2 * b + 1] = (float)(o1 == 0 ? c2 : c3);
    }
}

// ---------------------------------------------------------------------------
__global__ __launch_bounds__(256)
void linear_kernel(const float* __restrict__ X, const float* __restrict__ W,
                   const float* __restrict__ bias, float* __restrict__ out, int N)
{
    __shared__ float xs[512];
    const int m = blockIdx.x;
    for (int k = threadIdx.x; k < 512; k += 256) xs[k] = X[m * 512 + k];
    __syncthreads();

    const int n = blockIdx.y * 256 + threadIdx.x;
    if (n < N) {
        float a = bias[n];
#pragma unroll 8
        for (int k = 0; k < 512; k++)
            a = fmaf(xs[k], __ldg(&W[(size_t)k * N + n]), a);
        out[m * N + n] = a;
    }
}

// ---------------------------------------------------------------------------
// kernel_launch
// ---------------------------------------------------------------------------
extern "C" void kernel_launch(void* const* d_in, const int* in_sizes, int n_in,
                              void* d_out, int out_size)
{
    const float* x       = (const float*)d_in[0];
    const float* boxes   = (const float*)d_in[1];
    const int*   cat     = (const int*)  d_in[2];
    const float* conv5_w = (const float*)d_in[3];
    const float* re_w    = (const float*)d_in[4];
    const float* re_b    = (const float*)d_in[5];
    const float* oc1_w   = (const float*)d_in[6];
    const float* oc1_b   = (const float*)d_in[7];
    const float* oc2_w   = (const float*)d_in[8];
    const float* oc2_b   = (const float*)d_in[9];
    const float* pr1_w   = (const float*)d_in[10];
    const float* pr1_b   = (const float*)d_in[11];
    const float* pr2_w   = (const float*)d_in[12];
    const float* pr2_b   = (const float*)d_in[13];
    float* out = (float*)d_out;

    float *p_pooled, *p_objfeas, *p_hid_obj, *p_hid_cls;
    cudaGetSymbolAddress((void**)&p_pooled,  g_pooled);
    cudaGetSymbolAddress((void**)&p_objfeas, g_objfeas);
    cudaGetSymbolAddress((void**)&p_hid_obj, g_hid_obj);
    cudaGetSymbolAddress((void**)&p_hid_cls, g_hid_cls);

    cudaFuncSetAttribute(gemm1_mma, cudaFuncAttributeMaxDynamicSharedMemorySize, G1_SMEM);
    cudaFuncSetAttribute(gemm2_mma, cudaFuncAttributeMaxDynamicSharedMemorySize, G2_SMEM);

    // 0) weight pre-passes + zero (off critical path)
    wconv_kernel<<<(C_INR * C_INC + 511) / 512, 512>>>(conv5_w);
    rewt_kernel<<<dim3(K_FEATS / 32, C_INR / 32), dim3(32, 8)>>>(re_w);
    zero_kernel<<<(NROIS * C_INR + 255) / 256, 256>>>();

    // 1) big 1x1-conv GEMM (tf32 mma, 64x64 warp tiles)
    gemm1_mma<<<dim3(C_INR / 128, M_TOTAL / 128), 128, G1_SMEM>>>(x);

    // 2) ROI align (emits tf32-rounded feats in k' order)
    roi_kernel<<<NROIS, 128>>>(boxes);

    // 3) feats @ re_w on tensor cores, split-K=8 + atomics
    gemm2_mma<<<dim3(4, 4, G2_SPLITS), 256, G2_SMEM>>>();

    // 4) bias+relu+T-mean, NB-mean pool, obj selection + labels
    reduce_kernel<<<BB, 512>>>(re_b, cat, out, out_size);

    // 5) heads
    linear_kernel<<<dim3(2 * BB, 2), 256>>>(p_objfeas, oc1_w, oc1_b, p_hid_obj, 512);
    linear_kernel<<<dim3(2 * BB, 2), 256>>>(p_hid_obj, oc2_w, oc2_b, out + OUT_OBJCLS_OFF, NOBJ);
    linear_kernel<<<dim3(BB, 2), 256>>>(p_pooled, pr1_w, pr1_b, p_hid_cls, 512);
    linear_kernel<<<dim3(BB, 1), 256>>>(p_hid_cls, pr2_w, pr2_b, out, NCLS);
}

// round 7
// speedup vs baseline: 3.3077x; 1.0202x over previous
#include <cuda_runtime.h>
#include <cuda_bf16.h>
#include <math.h>
#include <stdint.h>

// ---------------------------------------------------------------------------
// Problem constants
// ---------------------------------------------------------------------------
#define BB        16
#define TT        8
#define NB        4
#define C_INC     2048       // C_IN
#define C_INR     512        // C_INNER
#define WW        14
#define HWP       196        // H*W
#define M_TOTAL   25088      // FRAMES*HW
#define K_FEATS   4608       // C_INNER*9
#define NROIS     512
#define NCLS      174
#define NOBJ      301

#define OUT_OBJCLS_OFF 2784
#define OUT_LABEL_OFF  12416

// ---------------------------------------------------------------------------
// Scratch
// ---------------------------------------------------------------------------
__device__ float g_fm[M_TOTAL * C_INR];        // [frame][hw][o]
__device__ float g_wtf[C_INR * C_INC];         // conv5_w tf32(RN), [n][k]
__device__ float g_rewt[C_INR * K_FEATS];      // re_w^T tf32, [n][k'], k'=c*9+bin
__device__ float g_feats[NROIS * K_FEATS];     // [roi][k'=c*9+bin], tf32-rounded
__device__ float g_regacc[NROIS * C_INR];
__device__ float g_pooled[BB * C_INR];
__device__ float g_objfeas[2 * BB * C_INR];
__device__ float g_hid_obj[2 * BB * C_INR];
__device__ float g_hid_cls[BB * C_INR];

// ---------------------------------------------------------------------------
// Helpers
// ---------------------------------------------------------------------------
__device__ __forceinline__ uint32_t smem_u32(const void* p) {
    uint32_t a;
    asm("{ .reg .u64 t; cvta.to.shared.u64 t, %1; cvt.u32.u64 %0, t; }"
        : "=r"(a) : "l"(p));
    return a;
}
__device__ __forceinline__ uint32_t f2tf32(float v) {
    uint32_t o;
    asm("cvt.rna.tf32.f32 %0, %1;" : "=r"(o) : "f"(v));
    return o;
}
#define LDS32(v, a) asm volatile("ld.shared.b32 %0, [%1];" : "=r"(v) : "r"(a))

__device__ __forceinline__ void mma_tf32(float& d0, float& d1, float& d2, float& d3,
                                         uint32_t a0, uint32_t a1, uint32_t a2, uint32_t a3,
                                         uint32_t b0, uint32_t b1)
{
    asm volatile(
        "mma.sync.aligned.m16n8k8.row.col.f32.tf32.tf32.f32 "
        "{%0,%1,%2,%3}, {%4,%5,%6,%7}, {%8,%9}, {%0,%1,%2,%3};"
        : "+f"(d0), "+f"(d1), "+f"(d2), "+f"(d3)
        : "r"(a0), "r"(a1), "r"(a2), "r"(a3), "r"(b0), "r"(b1));
}

// ---------------------------------------------------------------------------
// Weight pre-passes
// ---------------------------------------------------------------------------
__global__ void wconv_kernel(const float* __restrict__ w)
{
    int i = blockIdx.x * blockDim.x + threadIdx.x;
    if (i < C_INR * C_INC)
        g_wtf[i] = __uint_as_float(f2tf32(w[i]));
}

// Plain tiled transpose: g_rewt[n][r] = tf32( re_w[r][n] ),  r = k' = c*9+bin
__global__ void rewt_kernel(const float* __restrict__ rw)
{
    __shared__ float t[32][33];
    const int r0 = blockIdx.x * 32;     // row dim (4608)
    const int c0 = blockIdx.y * 32;     // n dim (512)
    const int cx = threadIdx.x;         // 0..31
    const int ty = threadIdx.y;         // 0..7
#pragma unroll
    for (int j = 0; j < 4; ++j) {
        int ry = ty + j * 8;
        t[ry][cx] = rw[(size_t)(r0 + ry) * C_INR + c0 + cx];
    }
    __syncthreads();
#pragma unroll
    for (int j = 0; j < 4; ++j) {
        int ry = ty + j * 8;
        g_rewt[(size_t)(c0 + ry) * K_FEATS + r0 + cx] =
            __uint_as_float(f2tf32(t[cx][ry]));
    }
}

// ---------------------------------------------------------------------------
// GEMM1 via mma.sync tf32: fm[m][n] = sum_k x(m,k) * w(n,k)
//   CTA tile 128x128, BK=32, 4 warps (2x2), warp tile 64x64.
//   grid (4 n-blocks, 196 m-blocks). SMEM 64KB double-buffered.
// ---------------------------------------------------------------------------
#define G1_ITERS   (C_INC / 32)     // 64
#define G1_SMEM    65536

__global__ void __launch_bounds__(128, 2) gemm1_mma(const float* __restrict__ x)
{
    extern __shared__ char sm[];
    const uint32_t sbase = smem_u32(sm);
    const int tid  = threadIdx.x;       // 0..127
    const int wid  = tid >> 5;
    const int lane = tid & 31;
    const int n0   = blockIdx.x * 128;
    const int m0   = blockIdx.y * 128;

    // ---- A loader: one m per thread, all 32 k's per iter
    const int lm = tid;
    const float* xb;
    {
        int mm = m0 + lm;
        int frame = mm / HWP;
        int hw = mm - frame * HWP;
        int b = frame >> 3, t = frame & 7;
        xb = x + (size_t)b * (C_INC * TT * HWP) + (size_t)t * HWP + hw;
    }
    const uint32_t a_row = (uint32_t)lm * 128;
    const uint32_t a_sw  = ((uint32_t)lm & 7) << 4;

    // ---- warp tile constants: 2x2 warps, warp 64x64
    const int wm = (wid >> 1) * 64;
    const int wn = (wid & 1) * 64;
    const int g  = lane >> 2;
    const int tg = lane & 3;
    const uint32_t frag_sw = ((uint32_t)g & 7) << 4;
    const uint32_t aoff0 = (uint32_t)(wm + g) * 128;
    const uint32_t boff0 = (uint32_t)(wn + g) * 128 + 32768u;

    float acc[4][8][4];
#pragma unroll
    for (int i = 0; i < 4; i++)
#pragma unroll
        for (int j = 0; j < 8; j++)
#pragma unroll
            for (int r = 0; r < 4; r++) acc[i][j][r] = 0.0f;

    float ar[32];

    // ---------------- prologue: stage k0 = 0 into buf 0
#pragma unroll
    for (int j = 0; j < 32; ++j)
        ar[j] = xb[(size_t)j * (TT * HWP)];
#pragma unroll
    for (int j4 = 0; j4 < 8; ++j4) {
        uint32_t dst = sbase + a_row + ((((uint32_t)j4 * 16)) ^ a_sw);
        uint4 v = make_uint4(f2tf32(ar[j4 * 4 + 0]), f2tf32(ar[j4 * 4 + 1]),
                             f2tf32(ar[j4 * 4 + 2]), f2tf32(ar[j4 * 4 + 3]));
        asm volatile("st.shared.v4.b32 [%0], {%1,%2,%3,%4};"
                     :: "r"(dst), "r"(v.x), "r"(v.y), "r"(v.z), "r"(v.w));
    }
#pragma unroll
    for (int i = 0; i < 8; ++i) {
        int idx = tid + i * 128;
        int n = idx >> 3, c = idx & 7;
        const float* src = g_wtf + (size_t)(n0 + n) * C_INC + c * 4;
        uint32_t dst = sbase + 32768u + (uint32_t)n * 128
                     + (((uint32_t)c * 16) ^ (((uint32_t)n & 7) << 4));
        asm volatile("cp.async.cg.shared.global [%0], [%1], 16;" :: "r"(dst), "l"(src));
    }
    asm volatile("cp.async.commit_group;" ::: "memory");

    // ---------------- main loop
    for (int s = 0; s < G1_ITERS; ++s) {
        const uint32_t bufo = (s & 1) ? 16384u : 0u;

        asm volatile("cp.async.wait_group 0;" ::: "memory");
        __syncthreads();

        if (s + 1 < G1_ITERS) {
            const int k0n = (s + 1) * 32;
#pragma unroll
            for (int j = 0; j < 32; ++j)
                ar[j] = xb[(size_t)(k0n + j) * (TT * HWP)];
            const uint32_t nb = (s + 1) & 1 ? 16384u : 0u;
#pragma unroll
            for (int i = 0; i < 8; ++i) {
                int idx = tid + i * 128;
                int n = idx >> 3, c = idx & 7;
                const float* src = g_wtf + (size_t)(n0 + n) * C_INC + k0n + c * 4;
                uint32_t dst = sbase + 32768u + nb + (uint32_t)n * 128
                             + (((uint32_t)c * 16) ^ (((uint32_t)n & 7) << 4));
                asm volatile("cp.async.cg.shared.global [%0], [%1], 16;" :: "r"(dst), "l"(src));
            }
            asm volatile("cp.async.commit_group;" ::: "memory");
        }

        // ---- compute on buffer s
        const uint32_t Ab = sbase + bufo;
        const uint32_t Bb = sbase + bufo;
#pragma unroll
        for (int kc = 0; kc < 4; ++kc) {
            const uint32_t u0 = (uint32_t)(kc * 32 + tg * 4) ^ frag_sw;
            const uint32_t u1 = (uint32_t)(kc * 32 + tg * 4 + 16) ^ frag_sw;

            uint32_t af[4][4];
#pragma unroll
            for (int mt = 0; mt < 4; ++mt) {
                uint32_t base = Ab + aoff0 + (uint32_t)mt * 2048;
                LDS32(af[mt][0], base + u0);
                LDS32(af[mt][1], base + 1024 + u0);
                LDS32(af[mt][2], base + u1);
                LDS32(af[mt][3], base + 1024 + u1);
            }
            uint32_t bf[8][2];
#pragma unroll
            for (int nt = 0; nt < 8; ++nt) {
                uint32_t base = Bb + boff0 + (uint32_t)nt * 1024;
                LDS32(bf[nt][0], base + u0);
                LDS32(bf[nt][1], base + u1);
            }
#pragma unroll
            for (int mt = 0; mt < 4; ++mt)
#pragma unroll
                for (int nt = 0; nt < 8; ++nt)
                    mma_tf32(acc[mt][nt][0], acc[mt][nt][1], acc[mt][nt][2], acc[mt][nt][3],
                             af[mt][0], af[mt][1], af[mt][2], af[mt][3],
                             bf[nt][0], bf[nt][1]);
        }

        // ---- store staged A into the other buffer
        if (s + 1 < G1_ITERS) {
            const uint32_t nb = (s + 1) & 1 ? 16384u : 0u;
#pragma unroll
            for (int j4 = 0; j4 < 8; ++j4) {
                uint32_t dst = sbase + nb + a_row + ((((uint32_t)j4 * 16)) ^ a_sw);
                uint4 v = make_uint4(f2tf32(ar[j4 * 4 + 0]), f2tf32(ar[j4 * 4 + 1]),
                                     f2tf32(ar[j4 * 4 + 2]), f2tf32(ar[j4 * 4 + 3]));
                asm volatile("st.shared.v4.b32 [%0], {%1,%2,%3,%4};"
                             :: "r"(dst), "r"(v.x), "r"(v.y), "r"(v.z), "r"(v.w));
            }
        }
    }

    // ---------------- epilogue
#pragma unroll
    for (int mt = 0; mt < 4; ++mt) {
#pragma unroll
        for (int nt = 0; nt < 8; ++nt) {
            int gm = m0 + wm + mt * 16 + g;
            int gn = n0 + wn + nt * 8 + tg * 2;
            float2 v0 = make_float2(acc[mt][nt][0], acc[mt][nt][1]);
            float2 v1 = make_float2(acc[mt][nt][2], acc[mt][nt][3]);
            *(float2*)&g_fm[(size_t)gm * C_INR + gn]       = v0;
            *(float2*)&g_fm[(size_t)(gm + 8) * C_INR + gn] = v1;
        }
    }
}

// ---------------------------------------------------------------------------
// ROI align: one block per ROI; writes feats in k' = c*9+bin order (tf32)
// ---------------------------------------------------------------------------
__global__ __launch_bounds__(128)
void roi_kernel(const float* __restrict__ boxes)
{
    const int r     = blockIdx.x;
    const int frame = r >> 2;
    const int c4    = threadIdx.x;

    const float* bx = boxes + r * 4;
    float cx = bx[0], cy = bx[1], w = bx[2], h = bx[3];

    float x1 = ((cx - w * 0.5f) * 224.0f) * 0.0625f;
    float y1 = ((cy - h * 0.5f) * 224.0f) * 0.0625f;
    float x2 = ((cx + w * 0.5f) * 224.0f) * 0.0625f;
    float y2 = ((cy + h * 0.5f) * 224.0f) * 0.0625f;

    float roi_w = fmaxf(x2 - x1, 1.0f);
    float roi_h = fmaxf(y2 - y1, 1.0f);
    float bw = roi_w * (1.0f / 3.0f);
    float bh = roi_h * (1.0f / 3.0f);

    float4 acc[9];
#pragma unroll
    for (int i = 0; i < 9; i++) acc[i] = make_float4(0.f, 0.f, 0.f, 0.f);

    const float* fmf = g_fm + (size_t)frame * HWP * C_INR + c4 * 4;

#pragma unroll
    for (int iy = 0; iy < 6; iy++) {
        float yy = y1 + (float)(iy >> 1) * bh + ((float)(iy & 1) + 0.5f) * bh * 0.5f;
        bool vy = (yy > -1.0f) && (yy < 14.0f);
        float yc = fminf(fmaxf(yy, 0.0f), 13.0f);
        int   yi0 = (int)floorf(yc);
        int   yi1 = min(yi0 + 1, 13);
        float ly = yc - (float)yi0;
        float hy = 1.0f - ly;

#pragma unroll
        for (int ix = 0; ix < 6; ix++) {
            float xx = x1 + (float)(ix >> 1) * bw + ((float)(ix & 1) + 0.5f) * bw * 0.5f;
            bool v = vy && (xx > -1.0f) && (xx < 14.0f);
            if (!v) continue;
            float xc = fminf(fmaxf(xx, 0.0f), 13.0f);
            int   xi0 = (int)floorf(xc);
            int   xi1 = min(xi0 + 1, 13);
            float lx = xc - (float)xi0;
            float hx = 1.0f - lx;

            float w00 = hy * hx, w01 = hy * lx, w10 = ly * hx, w11 = ly * lx;

            float4 p00 = *(const float4*)(fmf + (yi0 * WW + xi0) * C_INR);
            float4 p01 = *(const float4*)(fmf + (yi0 * WW + xi1) * C_INR);
            float4 p10 = *(const float4*)(fmf + (yi1 * WW + xi0) * C_INR);
            float4 p11 = *(const float4*)(fmf + (yi1 * WW + xi1) * C_INR);

            int bin = (iy >> 1) * 3 + (ix >> 1);
            acc[bin].x += w00 * p00.x + w01 * p01.x + w10 * p10.x + w11 * p11.x;
            acc[bin].y += w00 * p00.y + w01 * p01.y + w10 * p10.y + w11 * p11.y;
            acc[bin].z += w00 * p00.z + w01 * p01.z + w10 * p10.z + w11 * p11.z;
            acc[bin].w += w00 * p00.w + w01 * p01.w + w10 * p10.w + w11 * p11.w;
        }
    }

    // feats[k'] with k' = (c4*4+cc)*9 + bin -> thread-local 36 consecutive floats
    float tmp[36];
#pragma unroll
    for (int bin = 0; bin < 9; bin++) {
        tmp[0 * 9 + bin]  = __uint_as_float(f2tf32(acc[bin].x * 0.25f));
        tmp[1 * 9 + bin]  = __uint_as_float(f2tf32(acc[bin].y * 0.25f));
        tmp[2 * 9 + bin]  = __uint_as_float(f2tf32(acc[bin].z * 0.25f));
        tmp[3 * 9 + bin]  = __uint_as_float(f2tf32(acc[bin].w * 0.25f));
    }
    float* out = g_feats + (size_t)r * K_FEATS + c4 * 36;
#pragma unroll
    for (int q = 0; q < 9; q++)
        *(float4*)(out + q * 4) = *(float4*)&tmp[q * 4];
}

// ---------------------------------------------------------------------------
__global__ void zero_kernel()
{
    int i = blockIdx.x * blockDim.x + threadIdx.x;
    if (i < NROIS * C_INR) g_regacc[i] = 0.0f;
}

// ---------------------------------------------------------------------------
// GEMM2 via mma.sync tf32, split-K=8: regacc[m][n] += feats[m][k']*rewt[n][k']
// ---------------------------------------------------------------------------
#define G2_SPLITS 8
#define G2_KC     (K_FEATS / G2_SPLITS)   // 576
#define G2_ITERS  (G2_KC / 32)            // 18
#define G2_SMEM   65536

__global__ void __launch_bounds__(256, 2) gemm2_mma()
{
    extern __shared__ char sm[];
    const uint32_t sbase = smem_u32(sm);
    const int tid  = threadIdx.x;
    const int wid  = tid >> 5;
    const int lane = tid & 31;
    const int m0   = blockIdx.x * 128;
    const int n0   = blockIdx.y * 128;
    const int kb   = blockIdx.z * G2_KC;

    const int wm = (wid >> 2) * 64;
    const int wn = (wid & 3) * 32;
    const int g  = lane >> 2;
    const int tg = lane & 3;
    const uint32_t frag_sw = ((uint32_t)g & 7) << 4;
    const uint32_t aoff0 = (uint32_t)(wm + g) * 128;
    const uint32_t boff0 = (uint32_t)(wn + g) * 128 + 32768u;

    float acc[4][4][4];
#pragma unroll
    for (int i = 0; i < 4; i++)
#pragma unroll
        for (int j = 0; j < 4; j++)
#pragma unroll
            for (int r = 0; r < 4; r++) acc[i][j][r] = 0.0f;

    // ---------------- prologue: stage k = kb into buf 0
#pragma unroll
    for (int i = 0; i < 4; ++i) {
        int idx = tid + i * 256;
        int rr = idx >> 3, c = idx & 7;
        uint32_t sw = (((uint32_t)c * 16) ^ (((uint32_t)rr & 7) << 4));
        const float* asrc = g_feats + (size_t)(m0 + rr) * K_FEATS + kb + c * 4;
        const float* bsrc = g_rewt  + (size_t)(n0 + rr) * K_FEATS + kb + c * 4;
        uint32_t adst = sbase + (uint32_t)rr * 128 + sw;
        uint32_t bdst = sbase + 32768u + (uint32_t)rr * 128 + sw;
        asm volatile("cp.async.cg.shared.global [%0], [%1], 16;" :: "r"(adst), "l"(asrc));
        asm volatile("cp.async.cg.shared.global [%0], [%1], 16;" :: "r"(bdst), "l"(bsrc));
    }
    asm volatile("cp.async.commit_group;" ::: "memory");

    for (int s = 0; s < G2_ITERS; ++s) {
        const uint32_t bufo = (s & 1) ? 16384u : 0u;

        asm volatile("cp.async.wait_group 0;" ::: "memory");
        __syncthreads();

        if (s + 1 < G2_ITERS) {
            const int k0n = kb + (s + 1) * 32;
            const uint32_t nb = (s + 1) & 1 ? 16384u : 0u;
#pragma unroll
            for (int i = 0; i < 4; ++i) {
                int idx = tid + i * 256;
                int rr = idx >> 3, c = idx & 7;
                uint32_t sw = (((uint32_t)c * 16) ^ (((uint32_t)rr & 7) << 4));
                const float* asrc = g_feats + (size_t)(m0 + rr) * K_FEATS + k0n + c * 4;
                const float* bsrc = g_rewt  + (size_t)(n0 + rr) * K_FEATS + k0n + c * 4;
                uint32_t adst = sbase + nb + (uint32_t)rr * 128 + sw;
                uint32_t bdst = sbase + 32768u + nb + (uint32_t)rr * 128 + sw;
                asm volatile("cp.async.cg.shared.global [%0], [%1], 16;" :: "r"(adst), "l"(asrc));
                asm volatile("cp.async.cg.shared.global [%0], [%1], 16;" :: "r"(bdst), "l"(bsrc));
            }
            asm volatile("cp.async.commit_group;" ::: "memory");
        }

        const uint32_t Ab = sbase + bufo;
        const uint32_t Bb = sbase + bufo;
#pragma unroll
        for (int kc = 0; kc < 4; ++kc) {
            const uint32_t u0 = (uint32_t)(kc * 32 + tg * 4) ^ frag_sw;
            const uint32_t u1 = (uint32_t)(kc * 32 + tg * 4 + 16) ^ frag_sw;

            uint32_t af[4][4];
#pragma unroll
            for (int mt = 0; mt < 4; ++mt) {
                uint32_t base = Ab + aoff0 + (uint32_t)mt * 2048;
                LDS32(af[mt][0], base + u0);
                LDS32(af[mt][1], base + 1024 + u0);
                LDS32(af[mt][2], base + u1);
                LDS32(af[mt][3], base + 1024 + u1);
            }
            uint32_t bf[4][2];
#pragma unroll
            for (int nt = 0; nt < 4; ++nt) {
                uint32_t base = Bb + boff0 + (uint32_t)nt * 1024;
                LDS32(bf[nt][0], base + u0);
                LDS32(bf[nt][1], base + u1);
            }
#pragma unroll
            for (int mt = 0; mt < 4; ++mt)
#pragma unroll
                for (int nt = 0; nt < 4; ++nt)
                    mma_tf32(acc[mt][nt][0], acc[mt][nt][1], acc[mt][nt][2], acc[mt][nt][3],
                             af[mt][0], af[mt][1], af[mt][2], af[mt][3],
                             bf[nt][0], bf[nt][1]);
        }
    }

    // ---------------- epilogue: atomic accumulate (split-K)
#pragma unroll
    for (int mt = 0; mt < 4; ++mt) {
#pragma unroll
        for (int nt = 0; nt < 4; ++nt) {
            int gm = m0 + wm + mt * 16 + g;
            int gn = n0 + wn + nt * 8 + tg * 2;
            atomicAdd(&g_regacc[(size_t)gm * C_INR + gn],           acc[mt][nt][0]);
            atomicAdd(&g_regacc[(size_t)gm * C_INR + gn + 1],       acc[mt][nt][1]);
            atomicAdd(&g_regacc[(size_t)(gm + 8) * C_INR + gn],     acc[mt][nt][2]);
            atomicAdd(&g_regacc[(size_t)(gm + 8) * C_INR + gn + 1], acc[mt][nt][3]);
        }
    }
}

// ---------------------------------------------------------------------------
__global__ __launch_bounds__(512)
void reduce_kernel(const float* __restrict__ re_b, const int* __restrict__ cat,
                   float* __restrict__ out, int out_size)
{
    const int b = blockIdx.x;
    const int j = threadIdx.x;
    const float bias = re_b[j];

    float rm[NB];
    float p = 0.0f;
#pragma unroll
    for (int nb = 0; nb < NB; nb++) {
        float s = 0.0f;
#pragma unroll
        for (int t = 0; t < TT; t++) {
            int r = (b * TT + t) * NB + nb;
            s += fmaxf(g_regacc[(size_t)r * C_INR + j] + bias, 0.0f);
        }
        rm[nb] = s * 0.125f;
        p += rm[nb];
    }
    g_pooled[b * C_INR + j] = p * 0.25f;

    int c2 = cat[b * NB + 2];
    int c3 = cat[b * NB + 3];
    int o0 = (c2 == 0 && c3 != 0) ? 1 : 0;
    int o1 = 1 - o0;
    g_objfeas[(2 * b) * C_INR + j]     = rm[2 + o0];
    g_objfeas[(2 * b + 1) * C_INR + j] = rm[2 + o1];

    if (j == 0 && out_size >= OUT_LABEL_OFF + 2 * BB) {
        out[OUT_LABEL_OFF + 2 * b]     = (float)(o0 == 0 ? c2 : c3);
        out[OUT_LABEL_OFF + 2 * b + 1] = (float)(o1 == 0 ? c2 : c3);
    }
}

// ---------------------------------------------------------------------------
__global__ __launch_bounds__(256)
void linear_kernel(const float* __restrict__ X, const float* __restrict__ W,
                   const float* __restrict__ bias, float* __restrict__ out, int N)
{
    __shared__ float xs[512];
    const int m = blockIdx.x;
    for (int k = threadIdx.x; k < 512; k += 256) xs[k] = X[m * 512 + k];
    __syncthreads();

    const int n = blockIdx.y * 256 + threadIdx.x;
    if (n < N) {
        float a = bias[n];
#pragma unroll 8
        for (int k = 0; k < 512; k++)
            a = fmaf(xs[k], __ldg(&W[(size_t)k * N + n]), a);
        out[m * N + n] = a;
    }
}

// ---------------------------------------------------------------------------
// kernel_launch
// ---------------------------------------------------------------------------
extern "C" void kernel_launch(void* const* d_in, const int* in_sizes, int n_in,
                              void* d_out, int out_size)
{
    const float* x       = (const float*)d_in[0];
    const float* boxes   = (const float*)d_in[1];
    const int*   cat     = (const int*)  d_in[2];
    const float* conv5_w = (const float*)d_in[3];
    const float* re_w    = (const float*)d_in[4];
    const float* re_b    = (const float*)d_in[5];
    const float* oc1_w   = (const float*)d_in[6];
    const float* oc1_b   = (const float*)d_in[7];
    const float* oc2_w   = (const float*)d_in[8];
    const float* oc2_b   = (const float*)d_in[9];
    const float* pr1_w   = (const float*)d_in[10];
    const float* pr1_b   = (const float*)d_in[11];
    const float* pr2_w   = (const float*)d_in[12];
    const float* pr2_b   = (const float*)d_in[13];
    float* out = (float*)d_out;

    float *p_pooled, *p_objfeas, *p_hid_obj, *p_hid_cls;
    cudaGetSymbolAddress((void**)&p_pooled,  g_pooled);
    cudaGetSymbolAddress((void**)&p_objfeas, g_objfeas);
    cudaGetSymbolAddress((void**)&p_hid_obj, g_hid_obj);
    cudaGetSymbolAddress((void**)&p_hid_cls, g_hid_cls);

    cudaFuncSetAttribute(gemm1_mma, cudaFuncAttributeMaxDynamicSharedMemorySize, G1_SMEM);
    cudaFuncSetAttribute(gemm2_mma, cudaFuncAttributeMaxDynamicSharedMemorySize, G2_SMEM);

    // 0) weight pre-passes + zero (off critical path)
    wconv_kernel<<<(C_INR * C_INC + 511) / 512, 512>>>(conv5_w);
    rewt_kernel<<<dim3(K_FEATS / 32, C_INR / 32), dim3(32, 8)>>>(re_w);
    zero_kernel<<<(NROIS * C_INR + 255) / 256, 256>>>();

    // 1) big 1x1-conv GEMM (tf32 mma, 64x64 warp tiles)
    gemm1_mma<<<dim3(C_INR / 128, M_TOTAL / 128), 128, G1_SMEM>>>(x);

    // 2) ROI align (emits tf32-rounded feats in k' order)
    roi_kernel<<<NROIS, 128>>>(boxes);

    // 3) feats @ re_w on tensor cores, split-K=8 + atomics
    gemm2_mma<<<dim3(4, 4, G2_SPLITS), 256, G2_SMEM>>>();

    // 4) bias+relu+T-mean, NB-mean pool, obj selection + labels
    reduce_kernel<<<BB, 512>>>(re_b, cat, out, out_size);

    // 5) heads
    linear_kernel<<<dim3(2 * BB, 2), 256>>>(p_objfeas, oc1_w, oc1_b, p_hid_obj, 512);
    linear_kernel<<<dim3(2 * BB, 2), 256>>>(p_hid_obj, oc2_w, oc2_b, out + OUT_OBJCLS_OFF, NOBJ);
    linear_kernel<<<dim3(BB, 2), 256>>>(p_pooled, pr1_w, pr1_b, p_hid_cls, 512);
    linear_kernel<<<dim3(BB, 1), 256>>>(p_hid_cls, pr2_w, pr2_b, out, NCLS);
}